// round 1
// baseline (speedup 1.0000x reference)
#include <cuda_runtime.h>
#include <math.h>

#define BB 2
#define SS 2048
#define HH 4096
#define NH 32
#define NKV 8
#define HD 128

// Scratch (allocation-free rule: __device__ globals)
__device__ float g_q[(size_t)BB*SS*NH*HD];
__device__ float g_k[(size_t)BB*SS*NKV*HD];
__device__ float g_v[(size_t)BB*SS*NKV*HD];
__device__ float g_attn[(size_t)BB*SS*NH*HD];

// ---------------------------------------------------------------------------
// SGEMM: C[M,N] = A[M,K] @ B[K,N], all row-major, dims multiples of tiles.
// 128x128 tile, BK=16, 256 threads, 8x8 per thread.
// ---------------------------------------------------------------------------
__global__ __launch_bounds__(256) void sgemm128(const float* __restrict__ A,
                                                const float* __restrict__ B,
                                                float* __restrict__ C,
                                                int M, int N, int K) {
    const int BKt = 16;
    __shared__ float As[BKt * 132];   // transposed A tile, padded stride 132
    __shared__ float Bs[BKt * 128];

    int tid  = threadIdx.x;
    int row0 = (tid / 16) * 8;
    int col0 = (tid % 16) * 8;
    int bm = blockIdx.y * 128, bn = blockIdx.x * 128;

    float acc[8][8];
#pragma unroll
    for (int i = 0; i < 8; i++)
#pragma unroll
        for (int j = 0; j < 8; j++) acc[i][j] = 0.f;

    for (int k0 = 0; k0 < K; k0 += BKt) {
        // A tile: 128 rows x 16 k, store transposed As[k][m]
#pragma unroll
        for (int t = 0; t < 2; t++) {
            int id  = tid + t * 256;
            int ar  = id >> 2;
            int ac4 = (id & 3) * 4;
            float4 va = *(const float4*)&A[(size_t)(bm + ar) * K + k0 + ac4];
            As[(ac4 + 0) * 132 + ar] = va.x;
            As[(ac4 + 1) * 132 + ar] = va.y;
            As[(ac4 + 2) * 132 + ar] = va.z;
            As[(ac4 + 3) * 132 + ar] = va.w;
        }
        // B tile: 16 rows x 128 n
#pragma unroll
        for (int t = 0; t < 2; t++) {
            int id  = tid + t * 256;
            int br  = id >> 5;
            int bc4 = (id & 31) * 4;
            *(float4*)&Bs[br * 128 + bc4] =
                *(const float4*)&B[(size_t)(k0 + br) * N + bn + bc4];
        }
        __syncthreads();

#pragma unroll
        for (int kk = 0; kk < BKt; kk++) {
            float4 a0 = *(float4*)&As[kk * 132 + row0];
            float4 a1 = *(float4*)&As[kk * 132 + row0 + 4];
            float4 b0 = *(float4*)&Bs[kk * 128 + col0];
            float4 b1 = *(float4*)&Bs[kk * 128 + col0 + 4];
            float a[8] = {a0.x, a0.y, a0.z, a0.w, a1.x, a1.y, a1.z, a1.w};
            float b[8] = {b0.x, b0.y, b0.z, b0.w, b1.x, b1.y, b1.z, b1.w};
#pragma unroll
            for (int i = 0; i < 8; i++)
#pragma unroll
                for (int j = 0; j < 8; j++) acc[i][j] += a[i] * b[j];
        }
        __syncthreads();
    }

#pragma unroll
    for (int i = 0; i < 8; i++) {
        float4 c0 = {acc[i][0], acc[i][1], acc[i][2], acc[i][3]};
        float4 c1 = {acc[i][4], acc[i][5], acc[i][6], acc[i][7]};
        *(float4*)&C[(size_t)(bm + row0 + i) * N + bn + col0]     = c0;
        *(float4*)&C[(size_t)(bm + row0 + i) * N + bn + col0 + 4] = c1;
    }
}

// ---------------------------------------------------------------------------
// RoPE in-place on x: [B*S, nheads, HD]; cos/sin: [B*S, HD]
// out[d]    = x[d]*cos[d]    - x[d+64]*sin[d]        (d < 64)
// out[d+64] = x[d+64]*cos[d+64] + x[d]*sin[d+64]
// ---------------------------------------------------------------------------
__global__ void rope_kernel(float* __restrict__ x,
                            const float* __restrict__ cos_t,
                            const float* __restrict__ sin_t,
                            int nheads, int total) {
    int idx = blockIdx.x * blockDim.x + threadIdx.x;
    if (idx >= total) return;
    int d  = idx % (HD / 2);
    int h  = (idx / (HD / 2)) % nheads;
    int bs = idx / ((HD / 2) * nheads);

    float c0 = cos_t[(size_t)bs * HD + d];
    float s0 = sin_t[(size_t)bs * HD + d];
    float c1 = cos_t[(size_t)bs * HD + d + HD / 2];
    float s1 = sin_t[(size_t)bs * HD + d + HD / 2];

    float* px = x + ((size_t)bs * nheads + h) * HD;
    float x0 = px[d];
    float x1 = px[d + HD / 2];
    px[d]          = x0 * c0 - x1 * s0;
    px[d + HD / 2] = x1 * c1 + x0 * s1;
}

// ---------------------------------------------------------------------------
// Flash attention (fp32, online softmax). One CTA = (b, h, 64-row q block).
// BQ=BK=64. 256 threads as 16x16: ty -> 4 q rows, tx -> 4 score cols /
// 8 output d-cols. Row stats reduced over the 16 tx lanes via shfl.
// ---------------------------------------------------------------------------
#define BQ  64
#define BKT 64
#define HDP 132
#define BKP 68
#define FLASH_SMEM ((3 * BQ * HDP + BQ * BKP) * 4)

__global__ __launch_bounds__(256) void flash_attn(const float* __restrict__ Q,
                                                  const float* __restrict__ K,
                                                  const float* __restrict__ V,
                                                  float* __restrict__ O) {
    extern __shared__ float smf[];
    float* Qs = smf;                  // [BQ][HDP]
    float* Ks = Qs + BQ * HDP;        // [BKT][HDP]
    float* Vs = Ks + BKT * HDP;       // [BKT][HDP]
    float* Ps = Vs + BKT * HDP;       // [BQ][BKP]

    int tid = threadIdx.x;
    int qb  = blockIdx.x;
    int bh  = blockIdx.y;
    int b   = bh / NH, h = bh % NH;
    int hk  = h / (NH / NKV);
    int ty  = tid / 16, tx = tid % 16;
    int r0  = ty * 4, c0 = tx * 4, d0 = tx * 8;

    const float scale = rsqrtf((float)HD);

    // Load Q tile (64 x 128)
    const float* qbase = Q + (((size_t)(b * SS + qb * BQ)) * NH + h) * HD;
    for (int i = tid; i < BQ * HD / 4; i += 256) {
        int rr = (i * 4) / HD, cc = (i * 4) % HD;
        *(float4*)&Qs[rr * HDP + cc] =
            *(const float4*)&qbase[(size_t)rr * NH * HD + cc];
    }

    float m[4], l[4], acc[4][8];
#pragma unroll
    for (int i = 0; i < 4; i++) {
        m[i] = -1e30f;
        l[i] = 0.f;
#pragma unroll
        for (int j = 0; j < 8; j++) acc[i][j] = 0.f;
    }

    int nkt = qb + 1;   // causal: only k tiles up to the diagonal
    for (int kt = 0; kt < nkt; kt++) {
        __syncthreads();  // Qs ready (iter 0); Ps/Vs consumed (iters > 0)
        const float* kbase = K + (((size_t)(b * SS + kt * BKT)) * NKV + hk) * HD;
        const float* vbase = V + (((size_t)(b * SS + kt * BKT)) * NKV + hk) * HD;
        for (int i = tid; i < BKT * HD / 4; i += 256) {
            int rr = (i * 4) / HD, cc = (i * 4) % HD;
            *(float4*)&Ks[rr * HDP + cc] =
                *(const float4*)&kbase[(size_t)rr * NKV * HD + cc];
            *(float4*)&Vs[rr * HDP + cc] =
                *(const float4*)&vbase[(size_t)rr * NKV * HD + cc];
        }
        __syncthreads();

        // ---- scores: S = Q @ K^T (4x4 per thread) ----
        float sc[4][4];
#pragma unroll
        for (int i = 0; i < 4; i++)
#pragma unroll
            for (int j = 0; j < 4; j++) sc[i][j] = 0.f;

        for (int d = 0; d < HD; d++) {
            float qv[4], kv[4];
#pragma unroll
            for (int i = 0; i < 4; i++) qv[i] = Qs[(r0 + i) * HDP + d];
#pragma unroll
            for (int j = 0; j < 4; j++) kv[j] = Ks[(c0 + j) * HDP + d];
#pragma unroll
            for (int i = 0; i < 4; i++)
#pragma unroll
                for (int j = 0; j < 4; j++) sc[i][j] += qv[i] * kv[j];
        }

        // scale + causal mask
        int qg0 = qb * BQ + r0, kg0 = kt * BKT + c0;
#pragma unroll
        for (int i = 0; i < 4; i++)
#pragma unroll
            for (int j = 0; j < 4; j++) {
                sc[i][j] *= scale;
                if (kg0 + j > qg0 + i) sc[i][j] = -1e30f;
            }

        // online softmax per row (reduce over 16 tx lanes)
#pragma unroll
        for (int i = 0; i < 4; i++) {
            float rmax = fmaxf(fmaxf(sc[i][0], sc[i][1]),
                               fmaxf(sc[i][2], sc[i][3]));
#pragma unroll
            for (int o = 1; o < 16; o <<= 1)
                rmax = fmaxf(rmax, __shfl_xor_sync(0xffffffffu, rmax, o));
            float mnew = fmaxf(m[i], rmax);
            float corr = expf(m[i] - mnew);
            float rsum = 0.f;
#pragma unroll
            for (int j = 0; j < 4; j++) {
                float p = expf(sc[i][j] - mnew);
                sc[i][j] = p;
                rsum += p;
            }
#pragma unroll
            for (int o = 1; o < 16; o <<= 1)
                rsum += __shfl_xor_sync(0xffffffffu, rsum, o);
            l[i] = l[i] * corr + rsum;
            m[i] = mnew;
#pragma unroll
            for (int j = 0; j < 8; j++) acc[i][j] *= corr;
#pragma unroll
            for (int j = 0; j < 4; j++) Ps[(r0 + i) * BKP + c0 + j] = sc[i][j];
        }
        __syncthreads();

        // ---- acc += P @ V (4x8 per thread) ----
        for (int k = 0; k < BKT; k++) {
            float pv[4];
#pragma unroll
            for (int i = 0; i < 4; i++) pv[i] = Ps[(r0 + i) * BKP + k];
            float4 v0 = *(float4*)&Vs[k * HDP + d0];
            float4 v1 = *(float4*)&Vs[k * HDP + d0 + 4];
            float vv[8] = {v0.x, v0.y, v0.z, v0.w, v1.x, v1.y, v1.z, v1.w};
#pragma unroll
            for (int i = 0; i < 4; i++)
#pragma unroll
                for (int j = 0; j < 8; j++) acc[i][j] += pv[i] * vv[j];
        }
    }

    // epilogue: O = acc / l, layout [B,S,NH*HD]
    float* obase = O + (((size_t)(b * SS + qb * BQ)) * NH + h) * HD;
#pragma unroll
    for (int i = 0; i < 4; i++) {
        float inv = 1.f / l[i];
#pragma unroll
        for (int j = 0; j < 8; j++)
            obase[(size_t)(r0 + i) * NH * HD + d0 + j] = acc[i][j] * inv;
    }
}

// ---------------------------------------------------------------------------
// Launch
// ---------------------------------------------------------------------------
extern "C" void kernel_launch(void* const* d_in, const int* in_sizes, int n_in,
                              void* d_out, int out_size) {
    const float* hidden = (const float*)d_in[0];
    const float* cosv   = (const float*)d_in[1];
    const float* sinv   = (const float*)d_in[2];
    const float* wq     = (const float*)d_in[3];
    const float* wk     = (const float*)d_in[4];
    const float* wv     = (const float*)d_in[5];
    const float* wo     = (const float*)d_in[6];
    float* out = (float*)d_out;

    void *pq, *pk, *pv, *pattn;
    cudaGetSymbolAddress(&pq, g_q);
    cudaGetSymbolAddress(&pk, g_k);
    cudaGetSymbolAddress(&pv, g_v);
    cudaGetSymbolAddress(&pattn, g_attn);
    float* dq = (float*)pq;
    float* dk = (float*)pk;
    float* dv = (float*)pv;
    float* dattn = (float*)pattn;

    cudaFuncSetAttribute(flash_attn, cudaFuncAttributeMaxDynamicSharedMemorySize,
                         FLASH_SMEM);

    const int M = BB * SS;  // 4096
    dim3 blk(256);

    // QKV projections
    sgemm128<<<dim3(NH * HD / 128, M / 128), blk>>>(hidden, wq, dq, M, NH * HD, HH);
    sgemm128<<<dim3(NKV * HD / 128, M / 128), blk>>>(hidden, wk, dk, M, NKV * HD, HH);
    sgemm128<<<dim3(NKV * HD / 128, M / 128), blk>>>(hidden, wv, dv, M, NKV * HD, HH);

    // RoPE on q and k
    int tq = BB * SS * NH * (HD / 2);
    rope_kernel<<<(tq + 255) / 256, 256>>>(dq, cosv, sinv, NH, tq);
    int tk = BB * SS * NKV * (HD / 2);
    rope_kernel<<<(tk + 255) / 256, 256>>>(dk, cosv, sinv, NKV, tk);

    // Attention
    flash_attn<<<dim3(SS / BQ, BB * NH), 256, FLASH_SMEM>>>(dq, dk, dv, dattn);

    // Output projection
    sgemm128<<<dim3(HH / 128, M / 128), blk>>>(dattn, wo, out, M, HH, HH);
}

// round 2
// speedup vs baseline: 1.5663x; 1.5663x over previous
#include <cuda_runtime.h>
#include <math.h>

#define BB 2
#define SS 2048
#define HH 4096
#define NH 32
#define NKV 8
#define HD 128

// Scratch (allocation-free rule: __device__ globals)
__device__ float g_q[(size_t)BB*SS*NH*HD];
__device__ float g_k[(size_t)BB*SS*NKV*HD];
__device__ float g_v[(size_t)BB*SS*NKV*HD];
__device__ float g_attn[(size_t)BB*SS*NH*HD];

__device__ __forceinline__ float to_tf32(float x) {
    float y;
    asm("cvt.rna.tf32.f32 %0, %1;" : "=f"(y) : "f"(x));
    return y;
}

__device__ __forceinline__ void mma_tf32(float* d, const float* a, const float* b) {
    asm volatile(
        "mma.sync.aligned.m16n8k8.row.col.f32.tf32.tf32.f32 "
        "{%0,%1,%2,%3}, {%4,%5,%6,%7}, {%8,%9}, {%0,%1,%2,%3};"
        : "+f"(d[0]), "+f"(d[1]), "+f"(d[2]), "+f"(d[3])
        : "f"(a[0]), "f"(a[1]), "f"(a[2]), "f"(a[3]),
          "f"(b[0]), "f"(b[1]));
}

// ---------------------------------------------------------------------------
// TF32 tensor-core GEMM: C[M,N] = A[M,K] @ B[K,N], row-major.
// CTA tile 128x128, BK=32, 256 threads = 8 warps (2 M x 4 N), warp 64x32.
// mma.sync.m16n8k8.tf32, fp32 accumulate.
// ---------------------------------------------------------------------------
#define TBM 128
#define TBN 128
#define TBK 32
#define ASTR 36    // As row stride (floats): bank = (g*4+tg)%32, conflict-free
#define BSTR 136   // Bs row stride (floats): bank = (tg*8+g)%32, conflict-free

__global__ __launch_bounds__(256) void sgemm_tf32(const float* __restrict__ A,
                                                  const float* __restrict__ B,
                                                  float* __restrict__ C,
                                                  int M, int N, int K) {
    __shared__ float As[TBM * ASTR];
    __shared__ float Bs[TBK * BSTR];

    int tid  = threadIdx.x;
    int lane = tid & 31;
    int w    = tid >> 5;
    int wm   = w & 1;        // 2 warps along M
    int wn   = w >> 1;       // 4 warps along N
    int g    = lane >> 2;    // group id 0..7
    int tg   = lane & 3;     // thread-in-group 0..3

    int bm = blockIdx.y * TBM, bn = blockIdx.x * TBN;

    float acc[4][4][4];      // [mi][ni][reg]
#pragma unroll
    for (int i = 0; i < 4; i++)
#pragma unroll
        for (int j = 0; j < 4; j++)
#pragma unroll
            for (int r = 0; r < 4; r++) acc[i][j][r] = 0.f;

    for (int k0 = 0; k0 < K; k0 += TBK) {
        // Load A tile 128x32 (4 float4 per thread), convert to tf32
#pragma unroll
        for (int i = 0; i < 4; i++) {
            int t   = tid + i * 256;
            int ar  = t >> 3;
            int ac4 = (t & 7) * 4;
            float4 v = *(const float4*)&A[(size_t)(bm + ar) * K + k0 + ac4];
            As[ar * ASTR + ac4 + 0] = to_tf32(v.x);
            As[ar * ASTR + ac4 + 1] = to_tf32(v.y);
            As[ar * ASTR + ac4 + 2] = to_tf32(v.z);
            As[ar * ASTR + ac4 + 3] = to_tf32(v.w);
        }
        // Load B tile 32x128
#pragma unroll
        for (int i = 0; i < 4; i++) {
            int t   = tid + i * 256;
            int br  = t >> 5;
            int bc4 = (t & 31) * 4;
            float4 v = *(const float4*)&B[(size_t)(k0 + br) * N + bn + bc4];
            Bs[br * BSTR + bc4 + 0] = to_tf32(v.x);
            Bs[br * BSTR + bc4 + 1] = to_tf32(v.y);
            Bs[br * BSTR + bc4 + 2] = to_tf32(v.z);
            Bs[br * BSTR + bc4 + 3] = to_tf32(v.w);
        }
        __syncthreads();

#pragma unroll
        for (int kk = 0; kk < TBK / 8; kk++) {
            int k8 = kk * 8;
            float afr[4][4], bfr[4][2];
#pragma unroll
            for (int mi = 0; mi < 4; mi++) {
                int rb = wm * 64 + mi * 16;
                afr[mi][0] = As[(rb + g)     * ASTR + k8 + tg];
                afr[mi][1] = As[(rb + g + 8) * ASTR + k8 + tg];
                afr[mi][2] = As[(rb + g)     * ASTR + k8 + tg + 4];
                afr[mi][3] = As[(rb + g + 8) * ASTR + k8 + tg + 4];
            }
#pragma unroll
            for (int ni = 0; ni < 4; ni++) {
                int cb = wn * 32 + ni * 8;
                bfr[ni][0] = Bs[(k8 + tg)     * BSTR + cb + g];
                bfr[ni][1] = Bs[(k8 + tg + 4) * BSTR + cb + g];
            }
#pragma unroll
            for (int mi = 0; mi < 4; mi++)
#pragma unroll
                for (int ni = 0; ni < 4; ni++)
                    mma_tf32(acc[mi][ni], afr[mi], bfr[ni]);
        }
        __syncthreads();
    }

    // Epilogue: c0 @(g, 2tg), c1 @(g, 2tg+1), c2 @(g+8, 2tg), c3 @(g+8, 2tg+1)
#pragma unroll
    for (int mi = 0; mi < 4; mi++) {
#pragma unroll
        for (int ni = 0; ni < 4; ni++) {
            int row = bm + wm * 64 + mi * 16 + g;
            int col = bn + wn * 32 + ni * 8 + 2 * tg;
            float2 lo = {acc[mi][ni][0], acc[mi][ni][1]};
            float2 hi = {acc[mi][ni][2], acc[mi][ni][3]};
            *(float2*)&C[(size_t)row * N + col]       = lo;
            *(float2*)&C[(size_t)(row + 8) * N + col] = hi;
        }
    }
}

// ---------------------------------------------------------------------------
// RoPE in-place on x: [B*S, nheads, HD]; cos/sin: [B*S, HD]
// ---------------------------------------------------------------------------
__global__ void rope_kernel(float* __restrict__ x,
                            const float* __restrict__ cos_t,
                            const float* __restrict__ sin_t,
                            int nheads, int total) {
    int idx = blockIdx.x * blockDim.x + threadIdx.x;
    if (idx >= total) return;
    int d  = idx % (HD / 2);
    int h  = (idx / (HD / 2)) % nheads;
    int bs = idx / ((HD / 2) * nheads);

    float c0 = cos_t[(size_t)bs * HD + d];
    float s0 = sin_t[(size_t)bs * HD + d];
    float c1 = cos_t[(size_t)bs * HD + d + HD / 2];
    float s1 = sin_t[(size_t)bs * HD + d + HD / 2];

    float* px = x + ((size_t)bs * nheads + h) * HD;
    float x0 = px[d];
    float x1 = px[d + HD / 2];
    px[d]          = x0 * c0 - x1 * s0;
    px[d + HD / 2] = x1 * c1 + x0 * s1;
}

// ---------------------------------------------------------------------------
// Flash attention (fp32, online softmax). One CTA = (b, h, 64-row q block).
// ---------------------------------------------------------------------------
#define BQ  64
#define BKT 64
#define HDP 132
#define BKP 68
#define FLASH_SMEM ((3 * BQ * HDP + BQ * BKP) * 4)

__global__ __launch_bounds__(256) void flash_attn(const float* __restrict__ Q,
                                                  const float* __restrict__ K,
                                                  const float* __restrict__ V,
                                                  float* __restrict__ O) {
    extern __shared__ float smf[];
    float* Qs = smf;
    float* Ks = Qs + BQ * HDP;
    float* Vs = Ks + BKT * HDP;
    float* Ps = Vs + BKT * HDP;

    int tid = threadIdx.x;
    int qb  = blockIdx.x;
    int bh  = blockIdx.y;
    int b   = bh / NH, h = bh % NH;
    int hk  = h / (NH / NKV);
    int ty  = tid / 16, tx = tid % 16;
    int r0  = ty * 4, c0 = tx * 4, d0 = tx * 8;

    const float scale = rsqrtf((float)HD);

    const float* qbase = Q + (((size_t)(b * SS + qb * BQ)) * NH + h) * HD;
    for (int i = tid; i < BQ * HD / 4; i += 256) {
        int rr = (i * 4) / HD, cc = (i * 4) % HD;
        *(float4*)&Qs[rr * HDP + cc] =
            *(const float4*)&qbase[(size_t)rr * NH * HD + cc];
    }

    float m[4], l[4], acc[4][8];
#pragma unroll
    for (int i = 0; i < 4; i++) {
        m[i] = -1e30f;
        l[i] = 0.f;
#pragma unroll
        for (int j = 0; j < 8; j++) acc[i][j] = 0.f;
    }

    int nkt = qb + 1;
    for (int kt = 0; kt < nkt; kt++) {
        __syncthreads();
        const float* kbase = K + (((size_t)(b * SS + kt * BKT)) * NKV + hk) * HD;
        const float* vbase = V + (((size_t)(b * SS + kt * BKT)) * NKV + hk) * HD;
        for (int i = tid; i < BKT * HD / 4; i += 256) {
            int rr = (i * 4) / HD, cc = (i * 4) % HD;
            *(float4*)&Ks[rr * HDP + cc] =
                *(const float4*)&kbase[(size_t)rr * NKV * HD + cc];
            *(float4*)&Vs[rr * HDP + cc] =
                *(const float4*)&vbase[(size_t)rr * NKV * HD + cc];
        }
        __syncthreads();

        float sc[4][4];
#pragma unroll
        for (int i = 0; i < 4; i++)
#pragma unroll
            for (int j = 0; j < 4; j++) sc[i][j] = 0.f;

        for (int d = 0; d < HD; d++) {
            float qv[4], kv[4];
#pragma unroll
            for (int i = 0; i < 4; i++) qv[i] = Qs[(r0 + i) * HDP + d];
#pragma unroll
            for (int j = 0; j < 4; j++) kv[j] = Ks[(c0 + j) * HDP + d];
#pragma unroll
            for (int i = 0; i < 4; i++)
#pragma unroll
                for (int j = 0; j < 4; j++) sc[i][j] += qv[i] * kv[j];
        }

        int qg0 = qb * BQ + r0, kg0 = kt * BKT + c0;
#pragma unroll
        for (int i = 0; i < 4; i++)
#pragma unroll
            for (int j = 0; j < 4; j++) {
                sc[i][j] *= scale;
                if (kg0 + j > qg0 + i) sc[i][j] = -1e30f;
            }

#pragma unroll
        for (int i = 0; i < 4; i++) {
            float rmax = fmaxf(fmaxf(sc[i][0], sc[i][1]),
                               fmaxf(sc[i][2], sc[i][3]));
#pragma unroll
            for (int o = 1; o < 16; o <<= 1)
                rmax = fmaxf(rmax, __shfl_xor_sync(0xffffffffu, rmax, o));
            float mnew = fmaxf(m[i], rmax);
            float corr = expf(m[i] - mnew);
            float rsum = 0.f;
#pragma unroll
            for (int j = 0; j < 4; j++) {
                float p = expf(sc[i][j] - mnew);
                sc[i][j] = p;
                rsum += p;
            }
#pragma unroll
            for (int o = 1; o < 16; o <<= 1)
                rsum += __shfl_xor_sync(0xffffffffu, rsum, o);
            l[i] = l[i] * corr + rsum;
            m[i] = mnew;
#pragma unroll
            for (int j = 0; j < 8; j++) acc[i][j] *= corr;
#pragma unroll
            for (int j = 0; j < 4; j++) Ps[(r0 + i) * BKP + c0 + j] = sc[i][j];
        }
        __syncthreads();

        for (int k = 0; k < BKT; k++) {
            float pv[4];
#pragma unroll
            for (int i = 0; i < 4; i++) pv[i] = Ps[(r0 + i) * BKP + k];
            float4 v0 = *(float4*)&Vs[k * HDP + d0];
            float4 v1 = *(float4*)&Vs[k * HDP + d0 + 4];
            float vv[8] = {v0.x, v0.y, v0.z, v0.w, v1.x, v1.y, v1.z, v1.w};
#pragma unroll
            for (int i = 0; i < 4; i++)
#pragma unroll
                for (int j = 0; j < 8; j++) acc[i][j] += pv[i] * vv[j];
        }
    }

    float* obase = O + (((size_t)(b * SS + qb * BQ)) * NH + h) * HD;
#pragma unroll
    for (int i = 0; i < 4; i++) {
        float inv = 1.f / l[i];
#pragma unroll
        for (int j = 0; j < 8; j++)
            obase[(size_t)(r0 + i) * NH * HD + d0 + j] = acc[i][j] * inv;
    }
}

// ---------------------------------------------------------------------------
// Launch
// ---------------------------------------------------------------------------
extern "C" void kernel_launch(void* const* d_in, const int* in_sizes, int n_in,
                              void* d_out, int out_size) {
    const float* hidden = (const float*)d_in[0];
    const float* cosv   = (const float*)d_in[1];
    const float* sinv   = (const float*)d_in[2];
    const float* wq     = (const float*)d_in[3];
    const float* wk     = (const float*)d_in[4];
    const float* wv     = (const float*)d_in[5];
    const float* wo     = (const float*)d_in[6];
    float* out = (float*)d_out;

    void *pq, *pk, *pv, *pattn;
    cudaGetSymbolAddress(&pq, g_q);
    cudaGetSymbolAddress(&pk, g_k);
    cudaGetSymbolAddress(&pv, g_v);
    cudaGetSymbolAddress(&pattn, g_attn);
    float* dq = (float*)pq;
    float* dk = (float*)pk;
    float* dv = (float*)pv;
    float* dattn = (float*)pattn;

    cudaFuncSetAttribute(flash_attn, cudaFuncAttributeMaxDynamicSharedMemorySize,
                         FLASH_SMEM);

    const int M = BB * SS;  // 4096
    dim3 blk(256);

    // QKV projections (tf32 tensor cores)
    sgemm_tf32<<<dim3(NH * HD / TBN, M / TBM), blk>>>(hidden, wq, dq, M, NH * HD, HH);
    sgemm_tf32<<<dim3(NKV * HD / TBN, M / TBM), blk>>>(hidden, wk, dk, M, NKV * HD, HH);
    sgemm_tf32<<<dim3(NKV * HD / TBN, M / TBM), blk>>>(hidden, wv, dv, M, NKV * HD, HH);

    // RoPE on q and k
    int tq = BB * SS * NH * (HD / 2);
    rope_kernel<<<(tq + 255) / 256, 256>>>(dq, cosv, sinv, NH, tq);
    int tk = BB * SS * NKV * (HD / 2);
    rope_kernel<<<(tk + 255) / 256, 256>>>(dk, cosv, sinv, NKV, tk);

    // Attention (fp32 flash)
    flash_attn<<<dim3(SS / BQ, BB * NH), 256, FLASH_SMEM>>>(dq, dk, dv, dattn);

    // Output projection
    sgemm_tf32<<<dim3(HH / TBN, M / TBM), blk>>>(dattn, wo, out, M, HH, HH);
}

// round 4
// speedup vs baseline: 1.7458x; 1.1146x over previous
#include <cuda_runtime.h>
#include <math.h>
#include <stdint.h>

#define BB 2
#define SS 2048
#define HH 4096
#define NH 32
#define NKV 8
#define HD 128

#define NQKV (NH * HD + 2 * NKV * HD)   // 6144 fused output cols

// Scratch (allocation-free rule: __device__ globals)
__device__ float g_hs[(size_t)BB*SS*HH];          // tf32-rounded hidden
__device__ float g_q[(size_t)BB*SS*NH*HD];
__device__ float g_k[(size_t)BB*SS*NKV*HD];
__device__ float g_v[(size_t)BB*SS*NKV*HD];
__device__ float g_attn[(size_t)BB*SS*NH*HD];
__device__ float g_wT[(size_t)NQKV*HH];           // fused [6144][4096] K-major (tf32)
__device__ float g_woT[(size_t)HH*NH*HD];         // [4096][4096] K-major (tf32)

// ---------------------------------------------------------------------------
// helpers
// ---------------------------------------------------------------------------
__device__ __forceinline__ float to_tf32(float x) {
    float y;
    asm("cvt.rna.tf32.f32 %0, %1;" : "=f"(y) : "f"(x));
    return y;
}

__device__ __forceinline__ uint32_t smem_u32(const void* p) {
    uint32_t a;
    asm("{ .reg .u64 t; cvta.to.shared.u64 t, %1; cvt.u32.u64 %0, t; }"
        : "=r"(a) : "l"(p));
    return a;
}

__device__ __forceinline__ void mma_tf32(float* d, const float* a, const float* b) {
    asm volatile(
        "mma.sync.aligned.m16n8k8.row.col.f32.tf32.tf32.f32 "
        "{%0,%1,%2,%3}, {%4,%5,%6,%7}, {%8,%9}, {%0,%1,%2,%3};"
        : "+f"(d[0]), "+f"(d[1]), "+f"(d[2]), "+f"(d[3])
        : "f"(a[0]), "f"(a[1]), "f"(a[2]), "f"(a[3]),
          "f"(b[0]), "f"(b[1]));
}

#define CP_ASYNC16(dst, src) \
    asm volatile("cp.async.cg.shared.global [%0], [%1], 16;" \
        :: "r"(dst), "l"(src) : "memory")
#define CP_COMMIT() asm volatile("cp.async.commit_group;" ::: "memory")
#define CP_WAIT1()  asm volatile("cp.async.wait_group 1;" ::: "memory")

// ---------------------------------------------------------------------------
// TF32 HMMA GEMM, cp.async 3-stage pipeline.
// C = A[M,K] @ BT[N,K]^T. Both operands K-major, pre-rounded to tf32.
// CTA 128x128x32, 256 thr = 8 warps (2M x 4N), warp 64x32.
// Smem: per operand 128 rows x 128B, XOR swizzle seg^=(row&7).
// Output split into up to 3 regions at col n1, n2 (for fused QKV).
// ---------------------------------------------------------------------------
#define TBM 128
#define TBN 128
#define TBK 32
#define NSTG 3
#define OPND_B (TBM * TBK * 4)             // 16 KB
#define STAGE_B (2 * OPND_B)               // 32 KB
#define GEMM_SMEM (NSTG * STAGE_B)         // 96 KB

__device__ __forceinline__ float lds_sw(const char* base, int row, int k) {
    int seg = k >> 2, w = k & 3;
    return *(const float*)(base + row * 128 + ((seg ^ (row & 7)) << 4) + (w << 2));
}

__global__ __launch_bounds__(256, 2) void gemm_tf32p(
        const float* __restrict__ A, const float* __restrict__ BT,
        float* __restrict__ C0, float* __restrict__ C1, float* __restrict__ C2,
        int M, int N, int K, int n1, int n2, int ns0, int ns1, int ns2) {
    extern __shared__ char smem[];
    uint32_t sb = smem_u32(smem);

    int tid  = threadIdx.x;
    int lane = tid & 31;
    int w    = tid >> 5;
    int wm   = w & 1;
    int wn   = w >> 1;
    int g    = lane >> 2;
    int tg   = lane & 3;

    int bm = blockIdx.y * TBM, bn = blockIdx.x * TBN;

    float acc[4][4][4];
#pragma unroll
    for (int i = 0; i < 4; i++)
#pragma unroll
        for (int j = 0; j < 4; j++)
#pragma unroll
            for (int r = 0; r < 4; r++) acc[i][j][r] = 0.f;

    const int NC = K / TBK;

    // --- async chunk loader: 4 A-segs + 4 B-segs per thread ---
    auto load_chunk = [&](int i, int s) {
        int k0 = i * TBK;
        uint32_t stA = sb + s * STAGE_B;
        uint32_t stB = stA + OPND_B;
#pragma unroll
        for (int j = 0; j < 4; j++) {
            int lin = tid + j * 256;
            int r = lin >> 3, sg = lin & 7;
            uint32_t dA = stA + r * 128 + ((sg ^ (r & 7)) << 4);
            CP_ASYNC16(dA, &A[(size_t)(bm + r) * K + k0 + sg * 4]);
            uint32_t dB = stB + r * 128 + ((sg ^ (r & 7)) << 4);
            CP_ASYNC16(dB, &BT[(size_t)(bn + r) * K + k0 + sg * 4]);
        }
    };

    load_chunk(0, 0); CP_COMMIT();
    load_chunk(1, 1); CP_COMMIT();

    for (int i = 0; i < NC; i++) {
        CP_WAIT1();
        __syncthreads();
        if (i + 2 < NC) load_chunk(i + 2, (i + 2) % NSTG);
        CP_COMMIT();

        const char* cA = smem + (i % NSTG) * STAGE_B;
        const char* cB = cA + OPND_B;
#pragma unroll
        for (int kk = 0; kk < 4; kk++) {
            int k8 = kk * 8;
            float afr[4][4], bfr[4][2];
#pragma unroll
            for (int mi = 0; mi < 4; mi++) {
                int rb = wm * 64 + mi * 16;
                afr[mi][0] = lds_sw(cA, rb + g,     k8 + tg);
                afr[mi][1] = lds_sw(cA, rb + g + 8, k8 + tg);
                afr[mi][2] = lds_sw(cA, rb + g,     k8 + tg + 4);
                afr[mi][3] = lds_sw(cA, rb + g + 8, k8 + tg + 4);
            }
#pragma unroll
            for (int ni = 0; ni < 4; ni++) {
                int cb = wn * 32 + ni * 8;
                bfr[ni][0] = lds_sw(cB, cb + g, k8 + tg);
                bfr[ni][1] = lds_sw(cB, cb + g, k8 + tg + 4);
            }
#pragma unroll
            for (int mi = 0; mi < 4; mi++)
#pragma unroll
                for (int ni = 0; ni < 4; ni++)
                    mma_tf32(acc[mi][ni], afr[mi], bfr[ni]);
        }
        __syncthreads();
    }

    // region select (uniform per CTA; tiles never straddle n1/n2)
    float* Cp; int ns, coff;
    if (bn < n1)      { Cp = C0; ns = ns0; coff = bn; }
    else if (bn < n2) { Cp = C1; ns = ns1; coff = bn - n1; }
    else              { Cp = C2; ns = ns2; coff = bn - n2; }

#pragma unroll
    for (int mi = 0; mi < 4; mi++) {
#pragma unroll
        for (int ni = 0; ni < 4; ni++) {
            int row = bm + wm * 64 + mi * 16 + g;
            int col = coff + wn * 32 + ni * 8 + 2 * tg;
            float2 lo = {acc[mi][ni][0], acc[mi][ni][1]};
            float2 hi = {acc[mi][ni][2], acc[mi][ni][3]};
            *(float2*)&Cp[(size_t)row * ns + col]       = lo;
            *(float2*)&Cp[(size_t)(row + 8) * ns + col] = hi;
        }
    }
}

// ---------------------------------------------------------------------------
// Transpose with tf32 rounding: out[c][r] = tf32(in[r][c]); in [R,C], out [C,R]
// ---------------------------------------------------------------------------
__global__ void transpose_round(const float* __restrict__ in, float* __restrict__ out,
                                int R, int C) {
    __shared__ float t[32][33];
    int bx = blockIdx.x * 32, by = blockIdx.y * 32;
    int x = bx + threadIdx.x;
#pragma unroll
    for (int j = threadIdx.y; j < 32; j += 8)
        t[j][threadIdx.x] = in[(size_t)(by + j) * C + x];
    __syncthreads();
    int ox = by + threadIdx.x;
#pragma unroll
    for (int j = threadIdx.y; j < 32; j += 8)
        out[(size_t)(bx + j) * R + ox] = to_tf32(t[threadIdx.x][j]);
}

__global__ void round_copy(const float* __restrict__ in, float* __restrict__ out, int n4) {
    int i = blockIdx.x * 256 + threadIdx.x;
    if (i >= n4) return;
    float4 v = ((const float4*)in)[i];
    v.x = to_tf32(v.x); v.y = to_tf32(v.y); v.z = to_tf32(v.z); v.w = to_tf32(v.w);
    ((float4*)out)[i] = v;
}

// ---------------------------------------------------------------------------
// RoPE in-place on x: [B*S, nheads, HD]; cos/sin: [B*S, HD]
// ---------------------------------------------------------------------------
__global__ void rope_kernel(float* __restrict__ x,
                            const float* __restrict__ cos_t,
                            const float* __restrict__ sin_t,
                            int nheads, int total) {
    int idx = blockIdx.x * blockDim.x + threadIdx.x;
    if (idx >= total) return;
    int d  = idx % (HD / 2);
    int h  = (idx / (HD / 2)) % nheads;
    int bs = idx / ((HD / 2) * nheads);

    float c0 = cos_t[(size_t)bs * HD + d];
    float s0 = sin_t[(size_t)bs * HD + d];
    float c1 = cos_t[(size_t)bs * HD + d + HD / 2];
    float s1 = sin_t[(size_t)bs * HD + d + HD / 2];

    float* px = x + ((size_t)bs * nheads + h) * HD;
    float x0 = px[d];
    float x1 = px[d + HD / 2];
    px[d]          = x0 * c0 - x1 * s0;
    px[d + HD / 2] = x1 * c1 + x0 * s1;
}

// ---------------------------------------------------------------------------
// Flash attention (fp32, online softmax). One CTA = (b, h, 64-row q block).
// ---------------------------------------------------------------------------
#define BQ  64
#define BKT 64
#define HDP 132
#define BKP 68
#define FLASH_SMEM ((3 * BQ * HDP + BQ * BKP) * 4)

__global__ __launch_bounds__(256) void flash_attn(const float* __restrict__ Q,
                                                  const float* __restrict__ K,
                                                  const float* __restrict__ V,
                                                  float* __restrict__ O) {
    extern __shared__ float smf[];
    float* Qs = smf;
    float* Ks = Qs + BQ * HDP;
    float* Vs = Ks + BKT * HDP;
    float* Ps = Vs + BKT * HDP;

    int tid = threadIdx.x;
    int qb  = blockIdx.x;
    int bh  = blockIdx.y;
    int b   = bh / NH, h = bh % NH;
    int hk  = h / (NH / NKV);
    int ty  = tid / 16, tx = tid % 16;
    int r0  = ty * 4, c0 = tx * 4, d0 = tx * 8;

    const float scale = rsqrtf((float)HD);

    const float* qbase = Q + (((size_t)(b * SS + qb * BQ)) * NH + h) * HD;
    for (int i = tid; i < BQ * HD / 4; i += 256) {
        int rr = (i * 4) / HD, cc = (i * 4) % HD;
        *(float4*)&Qs[rr * HDP + cc] =
            *(const float4*)&qbase[(size_t)rr * NH * HD + cc];
    }

    float m[4], l[4], acc[4][8];
#pragma unroll
    for (int i = 0; i < 4; i++) {
        m[i] = -1e30f;
        l[i] = 0.f;
#pragma unroll
        for (int j = 0; j < 8; j++) acc[i][j] = 0.f;
    }

    int nkt = qb + 1;
    for (int kt = 0; kt < nkt; kt++) {
        __syncthreads();
        const float* kbase = K + (((size_t)(b * SS + kt * BKT)) * NKV + hk) * HD;
        const float* vbase = V + (((size_t)(b * SS + kt * BKT)) * NKV + hk) * HD;
        for (int i = tid; i < BKT * HD / 4; i += 256) {
            int rr = (i * 4) / HD, cc = (i * 4) % HD;
            *(float4*)&Ks[rr * HDP + cc] =
                *(const float4*)&kbase[(size_t)rr * NKV * HD + cc];
            *(float4*)&Vs[rr * HDP + cc] =
                *(const float4*)&vbase[(size_t)rr * NKV * HD + cc];
        }
        __syncthreads();

        float sc[4][4];
#pragma unroll
        for (int i = 0; i < 4; i++)
#pragma unroll
            for (int j = 0; j < 4; j++) sc[i][j] = 0.f;

        for (int d = 0; d < HD; d++) {
            float qv[4], kv[4];
#pragma unroll
            for (int i = 0; i < 4; i++) qv[i] = Qs[(r0 + i) * HDP + d];
#pragma unroll
            for (int j = 0; j < 4; j++) kv[j] = Ks[(c0 + j) * HDP + d];
#pragma unroll
            for (int i = 0; i < 4; i++)
#pragma unroll
                for (int j = 0; j < 4; j++) sc[i][j] += qv[i] * kv[j];
        }

        int qg0 = qb * BQ + r0, kg0 = kt * BKT + c0;
#pragma unroll
        for (int i = 0; i < 4; i++)
#pragma unroll
            for (int j = 0; j < 4; j++) {
                sc[i][j] *= scale;
                if (kg0 + j > qg0 + i) sc[i][j] = -1e30f;
            }

#pragma unroll
        for (int i = 0; i < 4; i++) {
            float rmax = fmaxf(fmaxf(sc[i][0], sc[i][1]),
                               fmaxf(sc[i][2], sc[i][3]));
#pragma unroll
            for (int o = 1; o < 16; o <<= 1)
                rmax = fmaxf(rmax, __shfl_xor_sync(0xffffffffu, rmax, o));
            float mnew = fmaxf(m[i], rmax);
            float corr = expf(m[i] - mnew);
            float rsum = 0.f;
#pragma unroll
            for (int j = 0; j < 4; j++) {
                float p = expf(sc[i][j] - mnew);
                sc[i][j] = p;
                rsum += p;
            }
#pragma unroll
            for (int o = 1; o < 16; o <<= 1)
                rsum += __shfl_xor_sync(0xffffffffu, rsum, o);
            l[i] = l[i] * corr + rsum;
            m[i] = mnew;
#pragma unroll
            for (int j = 0; j < 8; j++) acc[i][j] *= corr;
#pragma unroll
            for (int j = 0; j < 4; j++) Ps[(r0 + i) * BKP + c0 + j] = sc[i][j];
        }
        __syncthreads();

        for (int k = 0; k < BKT; k++) {
            float pv[4];
#pragma unroll
            for (int i = 0; i < 4; i++) pv[i] = Ps[(r0 + i) * BKP + k];
            float4 v0 = *(float4*)&Vs[k * HDP + d0];
            float4 v1 = *(float4*)&Vs[k * HDP + d0 + 4];
            float vv[8] = {v0.x, v0.y, v0.z, v0.w, v1.x, v1.y, v1.z, v1.w};
#pragma unroll
            for (int i = 0; i < 4; i++)
#pragma unroll
                for (int j = 0; j < 8; j++) acc[i][j] += pv[i] * vv[j];
        }
    }

    // epilogue: round to tf32 (feeds the HMMA O-projection)
    float* obase = O + (((size_t)(b * SS + qb * BQ)) * NH + h) * HD;
#pragma unroll
    for (int i = 0; i < 4; i++) {
        float inv = 1.f / l[i];
#pragma unroll
        for (int j = 0; j < 8; j++)
            obase[(size_t)(r0 + i) * NH * HD + d0 + j] = to_tf32(acc[i][j] * inv);
    }
}

// ---------------------------------------------------------------------------
// Launch
// ---------------------------------------------------------------------------
extern "C" void kernel_launch(void* const* d_in, const int* in_sizes, int n_in,
                              void* d_out, int out_size) {
    const float* hidden = (const float*)d_in[0];
    const float* cosv   = (const float*)d_in[1];
    const float* sinv   = (const float*)d_in[2];
    const float* wq     = (const float*)d_in[3];
    const float* wk     = (const float*)d_in[4];
    const float* wv     = (const float*)d_in[5];
    const float* wo     = (const float*)d_in[6];
    float* out = (float*)d_out;

    void *phs, *pq, *pk, *pv, *pattn, *pwT, *pwo;
    cudaGetSymbolAddress(&phs, g_hs);
    cudaGetSymbolAddress(&pq, g_q);
    cudaGetSymbolAddress(&pk, g_k);
    cudaGetSymbolAddress(&pv, g_v);
    cudaGetSymbolAddress(&pattn, g_attn);
    cudaGetSymbolAddress(&pwT, g_wT);
    cudaGetSymbolAddress(&pwo, g_woT);
    float* dhs = (float*)phs;
    float* dq = (float*)pq;
    float* dk = (float*)pk;
    float* dv = (float*)pv;
    float* dattn = (float*)pattn;
    float* dwT = (float*)pwT;
    float* dwoT = (float*)pwo;

    cudaFuncSetAttribute(gemm_tf32p, cudaFuncAttributeMaxDynamicSharedMemorySize,
                         GEMM_SMEM);
    cudaFuncSetAttribute(flash_attn, cudaFuncAttributeMaxDynamicSharedMemorySize,
                         FLASH_SMEM);

    const int M  = BB * SS;       // 4096
    const int NQ = NH * HD;       // 4096
    const int NK = NKV * HD;      // 1024

    // Pre-round inputs / transpose weights (once per launch, ~100us total)
    int n4 = BB * SS * HH / 4;
    round_copy<<<(n4 + 255) / 256, 256>>>(hidden, dhs, n4);
    transpose_round<<<dim3(NQ / 32, HH / 32), dim3(32, 8)>>>(wq, dwT, HH, NQ);
    transpose_round<<<dim3(NK / 32, HH / 32), dim3(32, 8)>>>(wk, dwT + (size_t)NQ * HH, HH, NK);
    transpose_round<<<dim3(NK / 32, HH / 32), dim3(32, 8)>>>(wv, dwT + (size_t)(NQ + NK) * HH, HH, NK);
    transpose_round<<<dim3(HH / 32, NQ / 32), dim3(32, 8)>>>(wo, dwoT, NQ, HH);

    // Fused QKV projection: N = 6144, split epilogue into q/k/v
    gemm_tf32p<<<dim3(NQKV / TBN, M / TBM), 256, GEMM_SMEM>>>(
        dhs, dwT, dq, dk, dv, M, NQKV, HH, NQ, NQ + NK, NQ, NK, NK);

    // RoPE
    int tq = BB * SS * NH * (HD / 2);
    rope_kernel<<<(tq + 255) / 256, 256>>>(dq, cosv, sinv, NH, tq);
    int tk = BB * SS * NKV * (HD / 2);
    rope_kernel<<<(tk + 255) / 256, 256>>>(dk, cosv, sinv, NKV, tk);

    // Attention (fp32 flash)
    flash_attn<<<dim3(SS / BQ, BB * NH), 256, FLASH_SMEM>>>(dq, dk, dv, dattn);

    // Output projection
    gemm_tf32p<<<dim3(HH / TBN, M / TBM), 256, GEMM_SMEM>>>(
        dattn, dwoT, out, out, out, M, HH, NQ, HH, HH, HH, HH, HH);
}

// round 6
// speedup vs baseline: 1.9790x; 1.1336x over previous
#include <cuda_runtime.h>
#include <cuda_fp16.h>
#include <math.h>
#include <stdint.h>

#define BB 2
#define SS 2048
#define HH 4096
#define NH 32
#define NKV 8
#define HD 128

#define NQKV (NH * HD + 2 * NKV * HD)   // 6144 fused output cols

// Scratch (allocation-free rule: __device__ globals)
__device__ __half g_hs[(size_t)BB*SS*HH];         // fp16 hidden
__device__ float  g_q[(size_t)BB*SS*NH*HD];
__device__ float  g_k[(size_t)BB*SS*NKV*HD];
__device__ float  g_v[(size_t)BB*SS*NKV*HD];
__device__ __half g_attn[(size_t)BB*SS*NH*HD];    // fp16 attn (O-proj input)
__device__ __half g_wT[(size_t)NQKV*HH];          // fused [6144][4096] K-major fp16
__device__ __half g_woT[(size_t)HH*NH*HD];        // [4096][4096] K-major fp16

// ---------------------------------------------------------------------------
// helpers
// ---------------------------------------------------------------------------
__device__ __forceinline__ uint32_t smem_u32(const void* p) {
    uint32_t a;
    asm("{ .reg .u64 t; cvta.to.shared.u64 t, %1; cvt.u32.u64 %0, t; }"
        : "=r"(a) : "l"(p));
    return a;
}

__device__ __forceinline__ void mma_f16(float* d, const uint32_t* a, const uint32_t* b) {
    asm volatile(
        "mma.sync.aligned.m16n8k16.row.col.f32.f16.f16.f32 "
        "{%0,%1,%2,%3}, {%4,%5,%6,%7}, {%8,%9}, {%0,%1,%2,%3};"
        : "+f"(d[0]), "+f"(d[1]), "+f"(d[2]), "+f"(d[3])
        : "r"(a[0]), "r"(a[1]), "r"(a[2]), "r"(a[3]),
          "r"(b[0]), "r"(b[1]));
}

#define CP_ASYNC16(dst, src) \
    asm volatile("cp.async.cg.shared.global [%0], [%1], 16;" \
        :: "r"(dst), "l"(src) : "memory")
#define CP_COMMIT() asm volatile("cp.async.commit_group;" ::: "memory")
#define CP_WAIT1()  asm volatile("cp.async.wait_group 1;" ::: "memory")

// ---------------------------------------------------------------------------
// FP16 HMMA GEMM, cp.async 3-stage pipeline.
// C = A[M,K] @ BT[N,K]^T. Both operands K-major fp16, fp32 accumulate.
// CTA 128x128x64(k-elems), 256 thr = 8 warps (2M x 4N), warp 64x32.
// Smem rows: 64 halves = 128B, XOR swizzle (16B seg) ^= (row & 7).
// ---------------------------------------------------------------------------
#define TBM 128
#define TBN 128
#define TBK 64
#define NSTG 3
#define OPND_B (TBM * TBK * 2)             // 16 KB
#define STAGE_B (2 * OPND_B)               // 32 KB
#define GEMM_SMEM (NSTG * STAGE_B)         // 96 KB

// load b32 (2 halves) at [row][kelem], kelem even
__device__ __forceinline__ uint32_t lds_h2(const char* base, int row, int kelem) {
    int byte = kelem * 2;
    int seg  = byte >> 4;
    return *(const uint32_t*)(base + row * 128 + ((seg ^ (row & 7)) << 4) + (byte & 15));
}

__global__ __launch_bounds__(256, 2) void gemm_f16p(
        const __half* __restrict__ A, const __half* __restrict__ BT,
        float* __restrict__ C0, float* __restrict__ C1, float* __restrict__ C2,
        int M, int N, int K, int n1, int n2, int ns0, int ns1, int ns2) {
    extern __shared__ char smem[];
    uint32_t sb = smem_u32(smem);

    int tid  = threadIdx.x;
    int lane = tid & 31;
    int w    = tid >> 5;
    int wm   = w & 1;
    int wn   = w >> 1;
    int g    = lane >> 2;
    int tg   = lane & 3;

    int bm = blockIdx.y * TBM, bn = blockIdx.x * TBN;

    float acc[4][4][4];
#pragma unroll
    for (int i = 0; i < 4; i++)
#pragma unroll
        for (int j = 0; j < 4; j++)
#pragma unroll
            for (int r = 0; r < 4; r++) acc[i][j][r] = 0.f;

    const int NC = K / TBK;

    // --- async chunk loader: 4 A-segs + 4 B-segs (16B each) per thread ---
    auto load_chunk = [&](int i, int s) {
        int k0 = i * TBK;
        uint32_t stA = sb + s * STAGE_B;
        uint32_t stB = stA + OPND_B;
#pragma unroll
        for (int j = 0; j < 4; j++) {
            int lin = tid + j * 256;
            int r = lin >> 3, sg = lin & 7;
            uint32_t dA = stA + r * 128 + ((sg ^ (r & 7)) << 4);
            CP_ASYNC16(dA, &A[(size_t)(bm + r) * K + k0 + sg * 8]);
            uint32_t dB = stB + r * 128 + ((sg ^ (r & 7)) << 4);
            CP_ASYNC16(dB, &BT[(size_t)(bn + r) * K + k0 + sg * 8]);
        }
    };

    load_chunk(0, 0); CP_COMMIT();
    load_chunk(1, 1); CP_COMMIT();

    for (int i = 0; i < NC; i++) {
        CP_WAIT1();
        __syncthreads();
        if (i + 2 < NC) load_chunk(i + 2, (i + 2) % NSTG);
        CP_COMMIT();

        const char* cA = smem + (i % NSTG) * STAGE_B;
        const char* cB = cA + OPND_B;
#pragma unroll
        for (int kk = 0; kk < 4; kk++) {
            int k16 = kk * 16;
            uint32_t afr[4][4], bfr[4][2];
#pragma unroll
            for (int mi = 0; mi < 4; mi++) {
                int rb = wm * 64 + mi * 16;
                afr[mi][0] = lds_h2(cA, rb + g,     k16 + 2 * tg);
                afr[mi][1] = lds_h2(cA, rb + g + 8, k16 + 2 * tg);
                afr[mi][2] = lds_h2(cA, rb + g,     k16 + 2 * tg + 8);
                afr[mi][3] = lds_h2(cA, rb + g + 8, k16 + 2 * tg + 8);
            }
#pragma unroll
            for (int ni = 0; ni < 4; ni++) {
                int cb = wn * 32 + ni * 8;
                bfr[ni][0] = lds_h2(cB, cb + g, k16 + 2 * tg);
                bfr[ni][1] = lds_h2(cB, cb + g, k16 + 2 * tg + 8);
            }
#pragma unroll
            for (int mi = 0; mi < 4; mi++)
#pragma unroll
                for (int ni = 0; ni < 4; ni++)
                    mma_f16(acc[mi][ni], afr[mi], bfr[ni]);
        }
        __syncthreads();
    }

    // region select (uniform per CTA; tiles never straddle n1/n2)
    float* Cp; int ns, coff;
    if (bn < n1)      { Cp = C0; ns = ns0; coff = bn; }
    else if (bn < n2) { Cp = C1; ns = ns1; coff = bn - n1; }
    else              { Cp = C2; ns = ns2; coff = bn - n2; }

#pragma unroll
    for (int mi = 0; mi < 4; mi++) {
#pragma unroll
        for (int ni = 0; ni < 4; ni++) {
            int row = bm + wm * 64 + mi * 16 + g;
            int col = coff + wn * 32 + ni * 8 + 2 * tg;
            float2 lo = {acc[mi][ni][0], acc[mi][ni][1]};
            float2 hi = {acc[mi][ni][2], acc[mi][ni][3]};
            *(float2*)&Cp[(size_t)row * ns + col]       = lo;
            *(float2*)&Cp[(size_t)(row + 8) * ns + col] = hi;
        }
    }
}

// ---------------------------------------------------------------------------
// FP16-output GEMM variant for the O projection (writes f32 out)
// (same kernel handles it — C regions are float; O-proj uses single region)
// ---------------------------------------------------------------------------

// Transpose + fp16 convert: out[c][r] = h(in[r][c]); in [R,C], out [C,R]
__global__ void transpose_h(const float* __restrict__ in, __half* __restrict__ out,
                            int R, int C) {
    __shared__ float t[32][33];
    int bx = blockIdx.x * 32, by = blockIdx.y * 32;
    int x = bx + threadIdx.x;
#pragma unroll
    for (int j = threadIdx.y; j < 32; j += 8)
        t[j][threadIdx.x] = in[(size_t)(by + j) * C + x];
    __syncthreads();
    int ox = by + threadIdx.x;
#pragma unroll
    for (int j = threadIdx.y; j < 32; j += 8)
        out[(size_t)(bx + j) * R + ox] = __float2half_rn(t[threadIdx.x][j]);
}

// fp32 -> fp16 copy, 8 elems/thread
__global__ void f2h_copy(const float* __restrict__ in, __half* __restrict__ out, int n8) {
    int i = blockIdx.x * 256 + threadIdx.x;
    if (i >= n8) return;
    float4 v0 = ((const float4*)in)[2 * i];
    float4 v1 = ((const float4*)in)[2 * i + 1];
    __half2* o = (__half2*)out + 4 * (size_t)i;
    o[0] = __floats2half2_rn(v0.x, v0.y);
    o[1] = __floats2half2_rn(v0.z, v0.w);
    o[2] = __floats2half2_rn(v1.x, v1.y);
    o[3] = __floats2half2_rn(v1.z, v1.w);
}

// ---------------------------------------------------------------------------
// RoPE in-place on x: [B*S, nheads, HD]; cos/sin: [B*S, HD]
// ---------------------------------------------------------------------------
__global__ void rope_kernel(float* __restrict__ x,
                            const float* __restrict__ cos_t,
                            const float* __restrict__ sin_t,
                            int nheads, int total) {
    int idx = blockIdx.x * blockDim.x + threadIdx.x;
    if (idx >= total) return;
    int d  = idx % (HD / 2);
    int h  = (idx / (HD / 2)) % nheads;
    int bs = idx / ((HD / 2) * nheads);

    float c0 = cos_t[(size_t)bs * HD + d];
    float s0 = sin_t[(size_t)bs * HD + d];
    float c1 = cos_t[(size_t)bs * HD + d + HD / 2];
    float s1 = sin_t[(size_t)bs * HD + d + HD / 2];

    float* px = x + ((size_t)bs * nheads + h) * HD;
    float x0 = px[d];
    float x1 = px[d + HD / 2];
    px[d]          = x0 * c0 - x1 * s0;
    px[d + HD / 2] = x1 * c1 + x0 * s1;
}

// ---------------------------------------------------------------------------
// Flash attention (fp32, online softmax). One CTA = (b, h, 64-row q block).
// Writes fp16 output (input of O projection).
// ---------------------------------------------------------------------------
#define BQ  64
#define BKT 64
#define HDP 132
#define BKP 68
#define FLASH_SMEM ((3 * BQ * HDP + BQ * BKP) * 4)

__global__ __launch_bounds__(256) void flash_attn(const float* __restrict__ Q,
                                                  const float* __restrict__ K,
                                                  const float* __restrict__ V,
                                                  __half* __restrict__ O) {
    extern __shared__ float smf[];
    float* Qs = smf;
    float* Ks = Qs + BQ * HDP;
    float* Vs = Ks + BKT * HDP;
    float* Ps = Vs + BKT * HDP;

    int tid = threadIdx.x;
    int qb  = blockIdx.x;
    int bh  = blockIdx.y;
    int b   = bh / NH, h = bh % NH;
    int hk  = h / (NH / NKV);
    int ty  = tid / 16, tx = tid % 16;
    int r0  = ty * 4, c0 = tx * 4, d0 = tx * 8;

    const float scale = rsqrtf((float)HD);

    const float* qbase = Q + (((size_t)(b * SS + qb * BQ)) * NH + h) * HD;
    for (int i = tid; i < BQ * HD / 4; i += 256) {
        int rr = (i * 4) / HD, cc = (i * 4) % HD;
        *(float4*)&Qs[rr * HDP + cc] =
            *(const float4*)&qbase[(size_t)rr * NH * HD + cc];
    }

    float m[4], l[4], acc[4][8];
#pragma unroll
    for (int i = 0; i < 4; i++) {
        m[i] = -1e30f;
        l[i] = 0.f;
#pragma unroll
        for (int j = 0; j < 8; j++) acc[i][j] = 0.f;
    }

    int nkt = qb + 1;
    for (int kt = 0; kt < nkt; kt++) {
        __syncthreads();
        const float* kbase = K + (((size_t)(b * SS + kt * BKT)) * NKV + hk) * HD;
        const float* vbase = V + (((size_t)(b * SS + kt * BKT)) * NKV + hk) * HD;
        for (int i = tid; i < BKT * HD / 4; i += 256) {
            int rr = (i * 4) / HD, cc = (i * 4) % HD;
            *(float4*)&Ks[rr * HDP + cc] =
                *(const float4*)&kbase[(size_t)rr * NKV * HD + cc];
            *(float4*)&Vs[rr * HDP + cc] =
                *(const float4*)&vbase[(size_t)rr * NKV * HD + cc];
        }
        __syncthreads();

        float sc[4][4];
#pragma unroll
        for (int i = 0; i < 4; i++)
#pragma unroll
            for (int j = 0; j < 4; j++) sc[i][j] = 0.f;

        for (int d = 0; d < HD; d++) {
            float qv[4], kv[4];
#pragma unroll
            for (int i = 0; i < 4; i++) qv[i] = Qs[(r0 + i) * HDP + d];
#pragma unroll
            for (int j = 0; j < 4; j++) kv[j] = Ks[(c0 + j) * HDP + d];
#pragma unroll
            for (int i = 0; i < 4; i++)
#pragma unroll
                for (int j = 0; j < 4; j++) sc[i][j] += qv[i] * kv[j];
        }

        int qg0 = qb * BQ + r0, kg0 = kt * BKT + c0;
#pragma unroll
        for (int i = 0; i < 4; i++)
#pragma unroll
            for (int j = 0; j < 4; j++) {
                sc[i][j] *= scale;
                if (kg0 + j > qg0 + i) sc[i][j] = -1e30f;
            }

#pragma unroll
        for (int i = 0; i < 4; i++) {
            float rmax = fmaxf(fmaxf(sc[i][0], sc[i][1]),
                               fmaxf(sc[i][2], sc[i][3]));
#pragma unroll
            for (int o = 1; o < 16; o <<= 1)
                rmax = fmaxf(rmax, __shfl_xor_sync(0xffffffffu, rmax, o));
            float mnew = fmaxf(m[i], rmax);
            float corr = expf(m[i] - mnew);
            float rsum = 0.f;
#pragma unroll
            for (int j = 0; j < 4; j++) {
                float p = expf(sc[i][j] - mnew);
                sc[i][j] = p;
                rsum += p;
            }
#pragma unroll
            for (int o = 1; o < 16; o <<= 1)
                rsum += __shfl_xor_sync(0xffffffffu, rsum, o);
            l[i] = l[i] * corr + rsum;
            m[i] = mnew;
#pragma unroll
            for (int j = 0; j < 8; j++) acc[i][j] *= corr;
#pragma unroll
            for (int j = 0; j < 4; j++) Ps[(r0 + i) * BKP + c0 + j] = sc[i][j];
        }
        __syncthreads();

        for (int k = 0; k < BKT; k++) {
            float pv[4];
#pragma unroll
            for (int i = 0; i < 4; i++) pv[i] = Ps[(r0 + i) * BKP + k];
            float4 v0 = *(float4*)&Vs[k * HDP + d0];
            float4 v1 = *(float4*)&Vs[k * HDP + d0 + 4];
            float vv[8] = {v0.x, v0.y, v0.z, v0.w, v1.x, v1.y, v1.z, v1.w};
#pragma unroll
            for (int i = 0; i < 4; i++)
#pragma unroll
                for (int j = 0; j < 8; j++) acc[i][j] += pv[i] * vv[j];
        }
    }

    // epilogue: fp16 output (O-projection input), 4x half2 stores per row
    __half* obase = O + (((size_t)(b * SS + qb * BQ)) * NH + h) * HD;
#pragma unroll
    for (int i = 0; i < 4; i++) {
        float inv = 1.f / l[i];
        __half2* op = (__half2*)(obase + (size_t)(r0 + i) * NH * HD + d0);
#pragma unroll
        for (int j = 0; j < 4; j++)
            op[j] = __floats2half2_rn(acc[i][2 * j] * inv, acc[i][2 * j + 1] * inv);
    }
}

// ---------------------------------------------------------------------------
// Launch
// ---------------------------------------------------------------------------
extern "C" void kernel_launch(void* const* d_in, const int* in_sizes, int n_in,
                              void* d_out, int out_size) {
    const float* hidden = (const float*)d_in[0];
    const float* cosv   = (const float*)d_in[1];
    const float* sinv   = (const float*)d_in[2];
    const float* wq     = (const float*)d_in[3];
    const float* wk     = (const float*)d_in[4];
    const float* wv     = (const float*)d_in[5];
    const float* wo     = (const float*)d_in[6];
    float* out = (float*)d_out;

    void *phs, *pq, *pk, *pv, *pattn, *pwT, *pwo;
    cudaGetSymbolAddress(&phs, g_hs);
    cudaGetSymbolAddress(&pq, g_q);
    cudaGetSymbolAddress(&pk, g_k);
    cudaGetSymbolAddress(&pv, g_v);
    cudaGetSymbolAddress(&pattn, g_attn);
    cudaGetSymbolAddress(&pwT, g_wT);
    cudaGetSymbolAddress(&pwo, g_woT);
    __half* dhs = (__half*)phs;
    float* dq = (float*)pq;
    float* dk = (float*)pk;
    float* dv = (float*)pv;
    __half* dattn = (__half*)pattn;
    __half* dwT = (__half*)pwT;
    __half* dwoT = (__half*)pwo;

    cudaFuncSetAttribute(gemm_f16p, cudaFuncAttributeMaxDynamicSharedMemorySize,
                         GEMM_SMEM);
    cudaFuncSetAttribute(flash_attn, cudaFuncAttributeMaxDynamicSharedMemorySize,
                         FLASH_SMEM);

    const int M  = BB * SS;       // 4096
    const int NQ = NH * HD;       // 4096
    const int NK = NKV * HD;      // 1024

    // Preprocess: fp16 hidden + fp16 transposed weights
    int n8 = BB * SS * HH / 8;
    f2h_copy<<<(n8 + 255) / 256, 256>>>(hidden, dhs, n8);
    transpose_h<<<dim3(NQ / 32, HH / 32), dim3(32, 8)>>>(wq, dwT, HH, NQ);
    transpose_h<<<dim3(NK / 32, HH / 32), dim3(32, 8)>>>(wk, dwT + (size_t)NQ * HH, HH, NK);
    transpose_h<<<dim3(NK / 32, HH / 32), dim3(32, 8)>>>(wv, dwT + (size_t)(NQ + NK) * HH, HH, NK);
    transpose_h<<<dim3(HH / 32, NQ / 32), dim3(32, 8)>>>(wo, dwoT, NQ, HH);

    // Fused QKV projection: N = 6144, split epilogue into q/k/v
    gemm_f16p<<<dim3(NQKV / TBN, M / TBM), 256, GEMM_SMEM>>>(
        dhs, dwT, dq, dk, dv, M, NQKV, HH, NQ, NQ + NK, NQ, NK, NK);

    // RoPE
    int tq = BB * SS * NH * (HD / 2);
    rope_kernel<<<(tq + 255) / 256, 256>>>(dq, cosv, sinv, NH, tq);
    int tk = BB * SS * NKV * (HD / 2);
    rope_kernel<<<(tk + 255) / 256, 256>>>(dk, cosv, sinv, NKV, tk);

    // Attention (fp32 flash, fp16 output)
    flash_attn<<<dim3(SS / BQ, BB * NH), 256, FLASH_SMEM>>>(dq, dk, dv, dattn);

    // Output projection
    gemm_f16p<<<dim3(HH / TBN, M / TBM), 256, GEMM_SMEM>>>(
        dattn, dwoT, out, out, out, M, HH, NQ, HH, HH, HH, HH, HH);
}

// round 8
// speedup vs baseline: 9.4475x; 4.7738x over previous
#include <cuda_runtime.h>
#include <cuda_fp16.h>
#include <math.h>
#include <stdint.h>

#define BB 2
#define SS 2048
#define HH 4096
#define NH 32
#define NKV 8
#define HD 128

#define NQKV (NH * HD + 2 * NKV * HD)   // 6144 fused output cols

// Scratch (allocation-free rule: __device__ globals)
__device__ __half g_hs[(size_t)BB*SS*HH];         // fp16 hidden
__device__ float  g_q[(size_t)BB*SS*NH*HD];       // f32 q (pre-RoPE)
__device__ float  g_k[(size_t)BB*SS*NKV*HD];
__device__ float  g_v[(size_t)BB*SS*NKV*HD];
__device__ __half g_qh[(size_t)BB*SS*NH*HD];      // fp16 q post-RoPE (pre-scaled)
__device__ __half g_kh[(size_t)BB*SS*NKV*HD];     // fp16 k post-RoPE
__device__ __half g_vT[(size_t)BB*NKV*HD*SS];     // fp16 V transposed [b,hk,d,s]
__device__ __half g_attn[(size_t)BB*SS*NH*HD];    // fp16 attn (O-proj input)
__device__ __half g_wT[(size_t)NQKV*HH];          // fused [6144][4096] K-major fp16
__device__ __half g_woT[(size_t)HH*NH*HD];        // [4096][4096] K-major fp16

// ---------------------------------------------------------------------------
// helpers
// ---------------------------------------------------------------------------
__device__ __forceinline__ uint32_t smem_u32(const void* p) {
    uint32_t a;
    asm("{ .reg .u64 t; cvta.to.shared.u64 t, %1; cvt.u32.u64 %0, t; }"
        : "=r"(a) : "l"(p));
    return a;
}

__device__ __forceinline__ void mma_f16(float* d, const uint32_t* a, const uint32_t* b) {
    asm volatile(
        "mma.sync.aligned.m16n8k16.row.col.f32.f16.f16.f32 "
        "{%0,%1,%2,%3}, {%4,%5,%6,%7}, {%8,%9}, {%0,%1,%2,%3};"
        : "+f"(d[0]), "+f"(d[1]), "+f"(d[2]), "+f"(d[3])
        : "r"(a[0]), "r"(a[1]), "r"(a[2]), "r"(a[3]),
          "r"(b[0]), "r"(b[1]));
}

#define CP_ASYNC16(dst, src) \
    asm volatile("cp.async.cg.shared.global [%0], [%1], 16;" \
        :: "r"(dst), "l"(src) : "memory")
#define CP_COMMIT() asm volatile("cp.async.commit_group;" ::: "memory")
#define CP_WAIT1()  asm volatile("cp.async.wait_group 1;" ::: "memory")

// ---------------------------------------------------------------------------
// FP16 HMMA GEMM, cp.async 3-stage pipeline (unchanged from R6).
// ---------------------------------------------------------------------------
#define TBM 128
#define TBN 128
#define TBK 64
#define NSTG 3
#define OPND_B (TBM * TBK * 2)
#define STAGE_B (2 * OPND_B)
#define GEMM_SMEM (NSTG * STAGE_B)

__device__ __forceinline__ uint32_t lds_h2(const char* base, int row, int kelem) {
    int byte = kelem * 2;
    int seg  = byte >> 4;
    return *(const uint32_t*)(base + row * 128 + ((seg ^ (row & 7)) << 4) + (byte & 15));
}

__global__ __launch_bounds__(256, 2) void gemm_f16p(
        const __half* __restrict__ A, const __half* __restrict__ BT,
        float* __restrict__ C0, float* __restrict__ C1, float* __restrict__ C2,
        int M, int N, int K, int n1, int n2, int ns0, int ns1, int ns2) {
    extern __shared__ char smem[];
    uint32_t sb = smem_u32(smem);

    int tid  = threadIdx.x;
    int lane = tid & 31;
    int w    = tid >> 5;
    int wm   = w & 1;
    int wn   = w >> 1;
    int g    = lane >> 2;
    int tg   = lane & 3;

    int bm = blockIdx.y * TBM, bn = blockIdx.x * TBN;

    float acc[4][4][4];
#pragma unroll
    for (int i = 0; i < 4; i++)
#pragma unroll
        for (int j = 0; j < 4; j++)
#pragma unroll
            for (int r = 0; r < 4; r++) acc[i][j][r] = 0.f;

    const int NC = K / TBK;

    auto load_chunk = [&](int i, int s) {
        int k0 = i * TBK;
        uint32_t stA = sb + s * STAGE_B;
        uint32_t stB = stA + OPND_B;
#pragma unroll
        for (int j = 0; j < 4; j++) {
            int lin = tid + j * 256;
            int r = lin >> 3, sg = lin & 7;
            uint32_t dA = stA + r * 128 + ((sg ^ (r & 7)) << 4);
            CP_ASYNC16(dA, &A[(size_t)(bm + r) * K + k0 + sg * 8]);
            uint32_t dB = stB + r * 128 + ((sg ^ (r & 7)) << 4);
            CP_ASYNC16(dB, &BT[(size_t)(bn + r) * K + k0 + sg * 8]);
        }
    };

    load_chunk(0, 0); CP_COMMIT();
    load_chunk(1, 1); CP_COMMIT();

    for (int i = 0; i < NC; i++) {
        CP_WAIT1();
        __syncthreads();
        if (i + 2 < NC) load_chunk(i + 2, (i + 2) % NSTG);
        CP_COMMIT();

        const char* cA = smem + (i % NSTG) * STAGE_B;
        const char* cB = cA + OPND_B;
#pragma unroll
        for (int kk = 0; kk < 4; kk++) {
            int k16 = kk * 16;
            uint32_t afr[4][4], bfr[4][2];
#pragma unroll
            for (int mi = 0; mi < 4; mi++) {
                int rb = wm * 64 + mi * 16;
                afr[mi][0] = lds_h2(cA, rb + g,     k16 + 2 * tg);
                afr[mi][1] = lds_h2(cA, rb + g + 8, k16 + 2 * tg);
                afr[mi][2] = lds_h2(cA, rb + g,     k16 + 2 * tg + 8);
                afr[mi][3] = lds_h2(cA, rb + g + 8, k16 + 2 * tg + 8);
            }
#pragma unroll
            for (int ni = 0; ni < 4; ni++) {
                int cb = wn * 32 + ni * 8;
                bfr[ni][0] = lds_h2(cB, cb + g, k16 + 2 * tg);
                bfr[ni][1] = lds_h2(cB, cb + g, k16 + 2 * tg + 8);
            }
#pragma unroll
            for (int mi = 0; mi < 4; mi++)
#pragma unroll
                for (int ni = 0; ni < 4; ni++)
                    mma_f16(acc[mi][ni], afr[mi], bfr[ni]);
        }
        __syncthreads();
    }

    float* Cp; int ns, coff;
    if (bn < n1)      { Cp = C0; ns = ns0; coff = bn; }
    else if (bn < n2) { Cp = C1; ns = ns1; coff = bn - n1; }
    else              { Cp = C2; ns = ns2; coff = bn - n2; }

#pragma unroll
    for (int mi = 0; mi < 4; mi++) {
#pragma unroll
        for (int ni = 0; ni < 4; ni++) {
            int row = bm + wm * 64 + mi * 16 + g;
            int col = coff + wn * 32 + ni * 8 + 2 * tg;
            float2 lo = {acc[mi][ni][0], acc[mi][ni][1]};
            float2 hi = {acc[mi][ni][2], acc[mi][ni][3]};
            *(float2*)&Cp[(size_t)row * ns + col]       = lo;
            *(float2*)&Cp[(size_t)(row + 8) * ns + col] = hi;
        }
    }
}

// ---------------------------------------------------------------------------
// Preprocessing kernels
// ---------------------------------------------------------------------------
__global__ void transpose_h(const float* __restrict__ in, __half* __restrict__ out,
                            int R, int C) {
    __shared__ float t[32][33];
    int bx = blockIdx.x * 32, by = blockIdx.y * 32;
    int x = bx + threadIdx.x;
#pragma unroll
    for (int j = threadIdx.y; j < 32; j += 8)
        t[j][threadIdx.x] = in[(size_t)(by + j) * C + x];
    __syncthreads();
    int ox = by + threadIdx.x;
#pragma unroll
    for (int j = threadIdx.y; j < 32; j += 8)
        out[(size_t)(bx + j) * R + ox] = __float2half_rn(t[threadIdx.x][j]);
}

__global__ void f2h_copy(const float* __restrict__ in, __half* __restrict__ out, int n8) {
    int i = blockIdx.x * 256 + threadIdx.x;
    if (i >= n8) return;
    float4 v0 = ((const float4*)in)[2 * i];
    float4 v1 = ((const float4*)in)[2 * i + 1];
    __half2* o = (__half2*)out + 4 * (size_t)i;
    o[0] = __floats2half2_rn(v0.x, v0.y);
    o[1] = __floats2half2_rn(v0.z, v0.w);
    o[2] = __floats2half2_rn(v1.x, v1.y);
    o[3] = __floats2half2_rn(v1.z, v1.w);
}

// V transpose: in g_v [b][s][hk][d] f32 -> out g_vT [b][hk][d][s] fp16
__global__ void v_transpose(const float* __restrict__ in, __half* __restrict__ out) {
    __shared__ float t[32][33];
    int s0 = blockIdx.x * 32, d0 = blockIdx.y * 32;
    int bhk = blockIdx.z;
    int b = bhk / NKV, hk = bhk % NKV;
#pragma unroll
    for (int j = threadIdx.y; j < 32; j += 8)
        t[j][threadIdx.x] =
            in[(((size_t)b * SS + s0 + j) * NKV + hk) * HD + d0 + threadIdx.x];
    __syncthreads();
#pragma unroll
    for (int j = threadIdx.y; j < 32; j += 8)
        out[(((size_t)b * NKV + hk) * HD + d0 + j) * SS + s0 + threadIdx.x] =
            __float2half_rn(t[threadIdx.x][j]);
}

// ---------------------------------------------------------------------------
// RoPE: read f32 x [B*S, nheads, HD], write fp16 out (same layout), x * scl.
// One thread per (bs, head, d2) with d2 in [0, 32): handles d=2*d2, 2*d2+1
// and partners d+64 -> 2x half2 stores.
// ---------------------------------------------------------------------------
__global__ void rope_h(const float* __restrict__ x, __half* __restrict__ out,
                       const float* __restrict__ cos_t, const float* __restrict__ sin_t,
                       int nheads, float scl, int total) {
    int idx = blockIdx.x * blockDim.x + threadIdx.x;
    if (idx >= total) return;
    int d2 = idx % 32;
    int h  = (idx / 32) % nheads;
    int bs = idx / (32 * nheads);
    int d  = 2 * d2;

    const float* cb = cos_t + (size_t)bs * HD;
    const float* sb = sin_t + (size_t)bs * HD;
    const float* px = x + ((size_t)bs * nheads + h) * HD;
    __half* po = out + ((size_t)bs * nheads + h) * HD;

    float xa0 = px[d],      xa1 = px[d + 1];
    float xb0 = px[d + 64], xb1 = px[d + 65];
    float lo0 = (xa0 * cb[d]      - xb0 * sb[d])      * scl;
    float lo1 = (xa1 * cb[d + 1]  - xb1 * sb[d + 1])  * scl;
    float hi0 = (xb0 * cb[d + 64] + xa0 * sb[d + 64]) * scl;
    float hi1 = (xb1 * cb[d + 65] + xa1 * sb[d + 65]) * scl;
    *(__half2*)(po + d)      = __floats2half2_rn(lo0, lo1);
    *(__half2*)(po + d + 64) = __floats2half2_rn(hi0, hi1);
}

// ---------------------------------------------------------------------------
// Flash attention, fp16 HMMA. CTA = (qb, b*h): 64 q-rows, 4 warps x m16.
// Q frags in registers; K smem [64][136] halves; VT smem [128][72] halves.
// Online softmax fp32; P repacked in-register as mma A-frags.
// Q pre-scaled by 1/sqrt(HD) in rope_h.
// ---------------------------------------------------------------------------
#define KS_STR 136
#define VS_STR 72
#define FLASH_SMEM ((64 * KS_STR + HD * VS_STR) * 2)

__global__ __launch_bounds__(128) void flash_h(const __half* __restrict__ Qh,
                                               const __half* __restrict__ Kh,
                                               const __half* __restrict__ VT,
                                               __half* __restrict__ O) {
    extern __shared__ __half sm[];
    __half* Ks = sm;               // [64][KS_STR]
    __half* Vs = sm + 64 * KS_STR; // [HD][VS_STR]

    int tid  = threadIdx.x;
    int lane = tid & 31;
    int wid  = tid >> 5;           // 0..3
    int g    = lane >> 2;
    int tg   = lane & 3;

    int qb = blockIdx.x;
    int bh = blockIdx.y;
    int b = bh / NH, h = bh % NH;
    int hk = h / (NH / NKV);

    // ---- stage Q tile into Ks buffer, build persistent Q fragments ----
    {
        const __half* qbase = Qh + (((size_t)b * SS + qb * 64) * NH + h) * HD;
#pragma unroll
        for (int i = 0; i < 8; i++) {
            int c = tid + i * 128;
            int r = c >> 4, in_ = c & 15;
            *(uint4*)&Ks[r * KS_STR + in_ * 8] =
                *(const uint4*)(qbase + (size_t)r * NH * HD + in_ * 8);
        }
    }
    __syncthreads();

    uint32_t qf[8][4];
    {
        int r0 = wid * 16 + g;
#pragma unroll
        for (int kc = 0; kc < 8; kc++) {
            qf[kc][0] = *(const uint32_t*)&Ks[r0 * KS_STR + kc * 16 + 2 * tg];
            qf[kc][1] = *(const uint32_t*)&Ks[(r0 + 8) * KS_STR + kc * 16 + 2 * tg];
            qf[kc][2] = *(const uint32_t*)&Ks[r0 * KS_STR + kc * 16 + 2 * tg + 8];
            qf[kc][3] = *(const uint32_t*)&Ks[(r0 + 8) * KS_STR + kc * 16 + 2 * tg + 8];
        }
    }
    __syncthreads();

    float m0 = -1e30f, m1 = -1e30f, l0 = 0.f, l1 = 0.f;
    float o[16][4];
#pragma unroll
    for (int nt = 0; nt < 16; nt++)
#pragma unroll
        for (int r = 0; r < 4; r++) o[nt][r] = 0.f;

    int row0 = qb * 64 + wid * 16 + g;
    int row1 = row0 + 8;

    for (int kt = 0; kt <= qb; kt++) {
        // ---- load K tile [64][128] and VT tile [128][64] ----
        {
            const __half* kb = Kh + (((size_t)b * SS + kt * 64) * NKV + hk) * HD;
#pragma unroll
            for (int i = 0; i < 8; i++) {
                int c = tid + i * 128;
                int r = c >> 4, in_ = c & 15;
                *(uint4*)&Ks[r * KS_STR + in_ * 8] =
                    *(const uint4*)(kb + (size_t)r * NKV * HD + in_ * 8);
            }
            const __half* vb = VT + (((size_t)b * NKV + hk) * HD) * SS + kt * 64;
#pragma unroll
            for (int i = 0; i < 8; i++) {
                int c = tid + i * 128;
                int r = c >> 3, in_ = c & 7;
                *(uint4*)&Vs[r * VS_STR + in_ * 8] =
                    *(const uint4*)(vb + (size_t)r * SS + in_ * 8);
            }
        }
        __syncthreads();

        // ---- scores S[16][64] per warp ----
        float s[8][4];
#pragma unroll
        for (int nt = 0; nt < 8; nt++)
#pragma unroll
            for (int r = 0; r < 4; r++) s[nt][r] = 0.f;

#pragma unroll
        for (int kc = 0; kc < 8; kc++) {
#pragma unroll
            for (int nt = 0; nt < 8; nt++) {
                uint32_t bfr[2];
                bfr[0] = *(const uint32_t*)&Ks[(nt * 8 + g) * KS_STR + kc * 16 + 2 * tg];
                bfr[1] = *(const uint32_t*)&Ks[(nt * 8 + g) * KS_STR + kc * 16 + 2 * tg + 8];
                mma_f16(s[nt], qf[kc], bfr);
            }
        }

        // ---- causal mask on diagonal tile ----
        if (kt == qb) {
#pragma unroll
            for (int nt = 0; nt < 8; nt++) {
                int colb = kt * 64 + nt * 8 + 2 * tg;
#pragma unroll
                for (int e = 0; e < 2; e++) {
                    if (colb + e > row0) s[nt][e]     = -1e30f;
                    if (colb + e > row1) s[nt][2 + e] = -1e30f;
                }
            }
        }

        // ---- online softmax (fp32) ----
        float mx0 = -1e30f, mx1 = -1e30f;
#pragma unroll
        for (int nt = 0; nt < 8; nt++) {
            mx0 = fmaxf(mx0, fmaxf(s[nt][0], s[nt][1]));
            mx1 = fmaxf(mx1, fmaxf(s[nt][2], s[nt][3]));
        }
        mx0 = fmaxf(mx0, __shfl_xor_sync(0xffffffffu, mx0, 1));
        mx0 = fmaxf(mx0, __shfl_xor_sync(0xffffffffu, mx0, 2));
        mx1 = fmaxf(mx1, __shfl_xor_sync(0xffffffffu, mx1, 1));
        mx1 = fmaxf(mx1, __shfl_xor_sync(0xffffffffu, mx1, 2));

        float mn0 = fmaxf(m0, mx0), mn1 = fmaxf(m1, mx1);
        float cr0 = __expf(m0 - mn0), cr1 = __expf(m1 - mn1);
        float lp0 = 0.f, lp1 = 0.f;
#pragma unroll
        for (int nt = 0; nt < 8; nt++) {
            s[nt][0] = __expf(s[nt][0] - mn0);
            s[nt][1] = __expf(s[nt][1] - mn0);
            s[nt][2] = __expf(s[nt][2] - mn1);
            s[nt][3] = __expf(s[nt][3] - mn1);
            lp0 += s[nt][0] + s[nt][1];
            lp1 += s[nt][2] + s[nt][3];
        }
        lp0 += __shfl_xor_sync(0xffffffffu, lp0, 1);
        lp0 += __shfl_xor_sync(0xffffffffu, lp0, 2);
        lp1 += __shfl_xor_sync(0xffffffffu, lp1, 1);
        lp1 += __shfl_xor_sync(0xffffffffu, lp1, 2);
        l0 = l0 * cr0 + lp0;
        l1 = l1 * cr1 + lp1;
        m0 = mn0; m1 = mn1;

#pragma unroll
        for (int nt = 0; nt < 16; nt++) {
            o[nt][0] *= cr0; o[nt][1] *= cr0;
            o[nt][2] *= cr1; o[nt][3] *= cr1;
        }

        // ---- pack P as A-frags (accum layout == A-frag layout) ----
        uint32_t pf[4][4];
#pragma unroll
        for (int kc = 0; kc < 4; kc++) {
            int t0 = 2 * kc, t1 = 2 * kc + 1;
            pf[kc][0] = __half2_raw(__floats2half2_rn(s[t0][0], s[t0][1])).x |
                        ((uint32_t)__half2_raw(__floats2half2_rn(s[t0][0], s[t0][1])).y << 16);
            // (use direct reinterpret instead)
            __half2 h00 = __floats2half2_rn(s[t0][0], s[t0][1]);
            __half2 h01 = __floats2half2_rn(s[t0][2], s[t0][3]);
            __half2 h10 = __floats2half2_rn(s[t1][0], s[t1][1]);
            __half2 h11 = __floats2half2_rn(s[t1][2], s[t1][3]);
            pf[kc][0] = *(uint32_t*)&h00;
            pf[kc][1] = *(uint32_t*)&h01;
            pf[kc][2] = *(uint32_t*)&h10;
            pf[kc][3] = *(uint32_t*)&h11;
        }

        // ---- O += P @ V (VT frags from smem) ----
#pragma unroll
        for (int nt = 0; nt < 16; nt++) {
#pragma unroll
            for (int kc = 0; kc < 4; kc++) {
                uint32_t bfr[2];
                bfr[0] = *(const uint32_t*)&Vs[(nt * 8 + g) * VS_STR + kc * 16 + 2 * tg];
                bfr[1] = *(const uint32_t*)&Vs[(nt * 8 + g) * VS_STR + kc * 16 + 2 * tg + 8];
                mma_f16(o[nt], pf[kc], bfr);
            }
        }
        __syncthreads();
    }

    // ---- epilogue: O /= l, write fp16 ----
    float inv0 = 1.f / l0, inv1 = 1.f / l1;
    __half* ob = O + (((size_t)b * SS) * NH + h) * HD;
#pragma unroll
    for (int nt = 0; nt < 16; nt++) {
        int col = nt * 8 + 2 * tg;
        __half2 v0 = __floats2half2_rn(o[nt][0] * inv0, o[nt][1] * inv0);
        __half2 v1 = __floats2half2_rn(o[nt][2] * inv1, o[nt][3] * inv1);
        *(__half2*)(ob + (size_t)row0 * NH * HD + col) = v0;
        *(__half2*)(ob + (size_t)row1 * NH * HD + col) = v1;
    }
}

// ---------------------------------------------------------------------------
// Launch. Order matters: ncu captures the 5th launch => gemm_f16p (QKV).
// ---------------------------------------------------------------------------
extern "C" void kernel_launch(void* const* d_in, const int* in_sizes, int n_in,
                              void* d_out, int out_size) {
    const float* hidden = (const float*)d_in[0];
    const float* cosv   = (const float*)d_in[1];
    const float* sinv   = (const float*)d_in[2];
    const float* wq     = (const float*)d_in[3];
    const float* wk     = (const float*)d_in[4];
    const float* wv     = (const float*)d_in[5];
    const float* wo     = (const float*)d_in[6];
    float* out = (float*)d_out;

    void *phs, *pq, *pk, *pv, *pqh, *pkh, *pvT, *pattn, *pwT, *pwo;
    cudaGetSymbolAddress(&phs, g_hs);
    cudaGetSymbolAddress(&pq, g_q);
    cudaGetSymbolAddress(&pk, g_k);
    cudaGetSymbolAddress(&pv, g_v);
    cudaGetSymbolAddress(&pqh, g_qh);
    cudaGetSymbolAddress(&pkh, g_kh);
    cudaGetSymbolAddress(&pvT, g_vT);
    cudaGetSymbolAddress(&pattn, g_attn);
    cudaGetSymbolAddress(&pwT, g_wT);
    cudaGetSymbolAddress(&pwo, g_woT);
    __half* dhs = (__half*)phs;
    float* dq = (float*)pq;
    float* dk = (float*)pk;
    float* dv = (float*)pv;
    __half* dqh = (__half*)pqh;
    __half* dkh = (__half*)pkh;
    __half* dvT = (__half*)pvT;
    __half* dattn = (__half*)pattn;
    __half* dwT = (__half*)pwT;
    __half* dwoT = (__half*)pwo;

    cudaFuncSetAttribute(gemm_f16p, cudaFuncAttributeMaxDynamicSharedMemorySize,
                         GEMM_SMEM);
    cudaFuncSetAttribute(flash_h, cudaFuncAttributeMaxDynamicSharedMemorySize,
                         FLASH_SMEM);

    const int M  = BB * SS;       // 4096
    const int NQ = NH * HD;       // 4096
    const int NK = NKV * HD;      // 1024

    // launches 1-4
    int n8 = BB * SS * HH / 8;
    f2h_copy<<<(n8 + 255) / 256, 256>>>(hidden, dhs, n8);
    transpose_h<<<dim3(NQ / 32, HH / 32), dim3(32, 8)>>>(wq, dwT, HH, NQ);
    transpose_h<<<dim3(NK / 32, HH / 32), dim3(32, 8)>>>(wk, dwT + (size_t)NQ * HH, HH, NK);
    transpose_h<<<dim3(NK / 32, HH / 32), dim3(32, 8)>>>(wv, dwT + (size_t)(NQ + NK) * HH, HH, NK);

    // launch 5: fused QKV projection (ncu-profiled)
    gemm_f16p<<<dim3(NQKV / TBN, M / TBM), 256, GEMM_SMEM>>>(
        dhs, dwT, dq, dk, dv, M, NQKV, HH, NQ, NQ + NK, NQ, NK, NK);

    // wo transpose (only needed before O-proj)
    transpose_h<<<dim3(HH / 32, NQ / 32), dim3(32, 8)>>>(wo, dwoT, NQ, HH);

    // RoPE -> fp16 (q pre-scaled by 1/sqrt(HD))
    const float scl = 1.f / sqrtf((float)HD);
    int tq = BB * SS * NH * 32;
    rope_h<<<(tq + 255) / 256, 256>>>(dq, dqh, cosv, sinv, NH, scl, tq);
    int tk = BB * SS * NKV * 32;
    rope_h<<<(tk + 255) / 256, 256>>>(dk, dkh, cosv, sinv, NKV, 1.f, tk);

    // V transpose to [b,hk,d,s] fp16
    v_transpose<<<dim3(SS / 32, HD / 32, BB * NKV), dim3(32, 8)>>>(dv, dvT);

    // Flash attention (fp16 HMMA)
    flash_h<<<dim3(SS / 64, BB * NH), 128, FLASH_SMEM>>>(dqh, dkh, dvT, dattn);

    // Output projection
    gemm_f16p<<<dim3(HH / TBN, M / TBM), 256, GEMM_SMEM>>>(
        dattn, dwoT, out, out, out, M, HH, NQ, HH, HH, HH, HH, HH);
}

// round 10
// speedup vs baseline: 10.4735x; 1.1086x over previous
#include <cuda_runtime.h>
#include <cuda_fp16.h>
#include <math.h>
#include <stdint.h>

#define BB 2
#define SS 2048
#define HH 4096
#define NH 32
#define NKV 8
#define HD 128

#define NQKV (NH * HD + 2 * NKV * HD)   // 6144 fused output cols

// Scratch (allocation-free rule: __device__ globals)
__device__ __half g_hs[(size_t)BB*SS*HH];         // fp16 hidden
__device__ float  g_q[(size_t)BB*SS*NH*HD];       // f32 q (pre-RoPE)
__device__ float  g_k[(size_t)BB*SS*NKV*HD];
__device__ float  g_v[(size_t)BB*SS*NKV*HD];
__device__ __half g_qh[(size_t)BB*SS*NH*HD];      // fp16 q post-RoPE (pre-scaled)
__device__ __half g_kh[(size_t)BB*SS*NKV*HD];     // fp16 k post-RoPE
__device__ __half g_vT[(size_t)BB*NKV*HD*SS];     // fp16 V transposed [b,hk,d,s]
__device__ __half g_attn[(size_t)BB*SS*NH*HD];    // fp16 attn (O-proj input)
__device__ __half g_wT[(size_t)NQKV*HH];          // fused [6144][4096] K-major fp16
__device__ __half g_woT[(size_t)HH*NH*HD];        // [4096][4096] K-major fp16

// ---------------------------------------------------------------------------
// helpers
// ---------------------------------------------------------------------------
__device__ __forceinline__ uint32_t smem_u32(const void* p) {
    uint32_t a;
    asm("{ .reg .u64 t; cvta.to.shared.u64 t, %1; cvt.u32.u64 %0, t; }"
        : "=r"(a) : "l"(p));
    return a;
}

__device__ __forceinline__ void mma_f16(float* d, const uint32_t* a, const uint32_t* b) {
    asm volatile(
        "mma.sync.aligned.m16n8k16.row.col.f32.f16.f16.f32 "
        "{%0,%1,%2,%3}, {%4,%5,%6,%7}, {%8,%9}, {%0,%1,%2,%3};"
        : "+f"(d[0]), "+f"(d[1]), "+f"(d[2]), "+f"(d[3])
        : "r"(a[0]), "r"(a[1]), "r"(a[2]), "r"(a[3]),
          "r"(b[0]), "r"(b[1]));
}

__device__ __forceinline__ void ldsm_x4(uint32_t* r, uint32_t addr) {
    asm volatile("ldmatrix.sync.aligned.m8n8.x4.shared.b16 {%0,%1,%2,%3}, [%4];"
        : "=r"(r[0]), "=r"(r[1]), "=r"(r[2]), "=r"(r[3]) : "r"(addr));
}

#define CP_ASYNC16(dst, src) \
    asm volatile("cp.async.cg.shared.global [%0], [%1], 16;" \
        :: "r"(dst), "l"(src) : "memory")
#define CP_COMMIT() asm volatile("cp.async.commit_group;" ::: "memory")
#define CP_WAIT1()  asm volatile("cp.async.wait_group 1;" ::: "memory")

// ---------------------------------------------------------------------------
// FP16 HMMA GEMM, cp.async 3-stage pipeline, ldmatrix fragment loads.
// ---------------------------------------------------------------------------
#define TBM 128
#define TBN 128
#define TBK 64
#define NSTG 3
#define OPND_B (TBM * TBK * 2)
#define STAGE_B (2 * OPND_B)
#define GEMM_SMEM (NSTG * STAGE_B)

__global__ __launch_bounds__(256, 2) void gemm_f16p(
        const __half* __restrict__ A, const __half* __restrict__ BT,
        float* __restrict__ C0, float* __restrict__ C1, float* __restrict__ C2,
        int M, int N, int K, int n1, int n2, int ns0, int ns1, int ns2) {
    extern __shared__ char smem[];
    uint32_t sb = smem_u32(smem);

    int tid  = threadIdx.x;
    int lane = tid & 31;
    int w    = tid >> 5;
    int wm   = w & 1;
    int wn   = w >> 1;
    int g    = lane >> 2;
    int tg   = lane & 3;

    int bm = blockIdx.y * TBM, bn = blockIdx.x * TBN;

    // ldmatrix per-lane geometry
    int l7  = lane & 7;
    int mlo = (lane >> 3) & 1;     // matrix pair selector bit0
    int mhi = lane >> 4;           // matrix pair selector bit1
    // A: mat0 rows-lo k-lo, mat1 rows-hi k-lo, mat2 rows-lo k-hi, mat3 rows-hi k-hi
    int aRowBase = wm * 64 + mlo * 8 + l7;     // + mi*16
    int aSegOff  = mhi;                        // + kk*2
    // B: mat0 n-lo k-lo, mat1 n-lo k-hi, mat2 n-hi k-lo, mat3 n-hi k-hi
    int bRowBase = wn * 32 + mhi * 8 + l7;     // + np*16
    int bSegOff  = mlo;                        // + kk*2

    float acc[4][4][4];
#pragma unroll
    for (int i = 0; i < 4; i++)
#pragma unroll
        for (int j = 0; j < 4; j++)
#pragma unroll
            for (int r = 0; r < 4; r++) acc[i][j][r] = 0.f;

    const int NC = K / TBK;

    auto load_chunk = [&](int i, int s) {
        int k0 = i * TBK;
        uint32_t stA = sb + s * STAGE_B;
        uint32_t stB = stA + OPND_B;
#pragma unroll
        for (int j = 0; j < 4; j++) {
            int lin = tid + j * 256;
            int r = lin >> 3, sg = lin & 7;
            uint32_t dA = stA + r * 128 + ((sg ^ (r & 7)) << 4);
            CP_ASYNC16(dA, &A[(size_t)(bm + r) * K + k0 + sg * 8]);
            uint32_t dB = stB + r * 128 + ((sg ^ (r & 7)) << 4);
            CP_ASYNC16(dB, &BT[(size_t)(bn + r) * K + k0 + sg * 8]);
        }
    };

    load_chunk(0, 0); CP_COMMIT();
    load_chunk(1, 1); CP_COMMIT();

    for (int i = 0; i < NC; i++) {
        CP_WAIT1();
        __syncthreads();
        if (i + 2 < NC) load_chunk(i + 2, (i + 2) % NSTG);
        CP_COMMIT();

        uint32_t cA = sb + (i % NSTG) * STAGE_B;
        uint32_t cB = cA + OPND_B;
#pragma unroll
        for (int kk = 0; kk < 4; kk++) {
            uint32_t afr[4][4], bfr[2][4];
#pragma unroll
            for (int mi = 0; mi < 4; mi++) {
                int row = aRowBase + mi * 16;
                int seg = kk * 2 + aSegOff;
                ldsm_x4(afr[mi], cA + row * 128 + (((seg ^ (row & 7)) & 7) << 4));
            }
#pragma unroll
            for (int np = 0; np < 2; np++) {
                int row = bRowBase + np * 16;
                int seg = kk * 2 + bSegOff;
                ldsm_x4(bfr[np], cB + row * 128 + (((seg ^ (row & 7)) & 7) << 4));
            }
#pragma unroll
            for (int mi = 0; mi < 4; mi++)
#pragma unroll
                for (int np = 0; np < 2; np++) {
                    mma_f16(acc[mi][2 * np],     afr[mi], &bfr[np][0]);
                    mma_f16(acc[mi][2 * np + 1], afr[mi], &bfr[np][2]);
                }
        }
        __syncthreads();
    }

    float* Cp; int ns, coff;
    if (bn < n1)      { Cp = C0; ns = ns0; coff = bn; }
    else if (bn < n2) { Cp = C1; ns = ns1; coff = bn - n1; }
    else              { Cp = C2; ns = ns2; coff = bn - n2; }

#pragma unroll
    for (int mi = 0; mi < 4; mi++) {
#pragma unroll
        for (int ni = 0; ni < 4; ni++) {
            int row = bm + wm * 64 + mi * 16 + g;
            int col = coff + wn * 32 + ni * 8 + 2 * tg;
            float2 lo = {acc[mi][ni][0], acc[mi][ni][1]};
            float2 hi = {acc[mi][ni][2], acc[mi][ni][3]};
            *(float2*)&Cp[(size_t)row * ns + col]       = lo;
            *(float2*)&Cp[(size_t)(row + 8) * ns + col] = hi;
        }
    }
}

// ---------------------------------------------------------------------------
// Preprocessing kernels
// ---------------------------------------------------------------------------
__global__ void transpose_h(const float* __restrict__ in, __half* __restrict__ out,
                            int R, int C) {
    __shared__ float t[32][33];
    int bx = blockIdx.x * 32, by = blockIdx.y * 32;
    int x = bx + threadIdx.x;
#pragma unroll
    for (int j = threadIdx.y; j < 32; j += 8)
        t[j][threadIdx.x] = in[(size_t)(by + j) * C + x];
    __syncthreads();
    int ox = by + threadIdx.x;
#pragma unroll
    for (int j = threadIdx.y; j < 32; j += 8)
        out[(size_t)(bx + j) * R + ox] = __float2half_rn(t[threadIdx.x][j]);
}

__global__ void f2h_copy(const float* __restrict__ in, __half* __restrict__ out, int n8) {
    int i = blockIdx.x * 256 + threadIdx.x;
    if (i >= n8) return;
    float4 v0 = ((const float4*)in)[2 * i];
    float4 v1 = ((const float4*)in)[2 * i + 1];
    __half2* o = (__half2*)out + 4 * (size_t)i;
    o[0] = __floats2half2_rn(v0.x, v0.y);
    o[1] = __floats2half2_rn(v0.z, v0.w);
    o[2] = __floats2half2_rn(v1.x, v1.y);
    o[3] = __floats2half2_rn(v1.z, v1.w);
}

// V transpose: in g_v [b][s][hk][d] f32 -> out g_vT [b][hk][d][s] fp16
__global__ void v_transpose(const float* __restrict__ in, __half* __restrict__ out) {
    __shared__ float t[32][33];
    int s0 = blockIdx.x * 32, d0 = blockIdx.y * 32;
    int bhk = blockIdx.z;
    int b = bhk / NKV, hk = bhk % NKV;
#pragma unroll
    for (int j = threadIdx.y; j < 32; j += 8)
        t[j][threadIdx.x] =
            in[(((size_t)b * SS + s0 + j) * NKV + hk) * HD + d0 + threadIdx.x];
    __syncthreads();
#pragma unroll
    for (int j = threadIdx.y; j < 32; j += 8)
        out[(((size_t)b * NKV + hk) * HD + d0 + j) * SS + s0 + threadIdx.x] =
            __float2half_rn(t[threadIdx.x][j]);
}

// ---------------------------------------------------------------------------
// RoPE: read f32 x [B*S, nheads, HD], write fp16 out (same layout), x * scl.
// ---------------------------------------------------------------------------
__global__ void rope_h(const float* __restrict__ x, __half* __restrict__ out,
                       const float* __restrict__ cos_t, const float* __restrict__ sin_t,
                       int nheads, float scl, int total) {
    int idx = blockIdx.x * blockDim.x + threadIdx.x;
    if (idx >= total) return;
    int d2 = idx % 32;
    int h  = (idx / 32) % nheads;
    int bs = idx / (32 * nheads);
    int d  = 2 * d2;

    const float* cb = cos_t + (size_t)bs * HD;
    const float* sb = sin_t + (size_t)bs * HD;
    const float* px = x + ((size_t)bs * nheads + h) * HD;
    __half* po = out + ((size_t)bs * nheads + h) * HD;

    float xa0 = px[d],      xa1 = px[d + 1];
    float xb0 = px[d + 64], xb1 = px[d + 65];
    float lo0 = (xa0 * cb[d]      - xb0 * sb[d])      * scl;
    float lo1 = (xa1 * cb[d + 1]  - xb1 * sb[d + 1])  * scl;
    float hi0 = (xb0 * cb[d + 64] + xa0 * sb[d + 64]) * scl;
    float hi1 = (xb1 * cb[d + 65] + xa1 * sb[d + 65]) * scl;
    *(__half2*)(po + d)      = __floats2half2_rn(lo0, lo1);
    *(__half2*)(po + d + 64) = __floats2half2_rn(hi0, hi1);
}

// ---------------------------------------------------------------------------
// Flash attention, fp16 HMMA with ldmatrix fragment loads.
// Padded strides: Ks 136 halves (272B), Vs 72 halves (144B) -> ldmatrix
// conflict-free (16r mod 128 distinct).
// ---------------------------------------------------------------------------
#define KS_STR 136
#define VS_STR 72
#define FLASH_SMEM ((64 * KS_STR + HD * VS_STR) * 2)

__global__ __launch_bounds__(128) void flash_h(const __half* __restrict__ Qh,
                                               const __half* __restrict__ Kh,
                                               const __half* __restrict__ VT,
                                               __half* __restrict__ O) {
    extern __shared__ __half sm[];
    __half* Ks = sm;               // [64][KS_STR]
    __half* Vs = sm + 64 * KS_STR; // [HD][VS_STR]
    uint32_t ksb = smem_u32(Ks);
    uint32_t vsb = smem_u32(Vs);

    int tid  = threadIdx.x;
    int lane = tid & 31;
    int wid  = tid >> 5;           // 0..3
    int g    = lane >> 2;
    int tg   = lane & 3;
    int l7   = lane & 7;
    int mlo  = (lane >> 3) & 1;
    int mhi  = lane >> 4;

    int qb = blockIdx.x;
    int bh = blockIdx.y;
    int b = bh / NH, h = bh % NH;
    int hk = h / (NH / NKV);

    // ---- stage Q tile into Ks buffer, build persistent Q fragments ----
    {
        const __half* qbase = Qh + (((size_t)b * SS + qb * 64) * NH + h) * HD;
#pragma unroll
        for (int i = 0; i < 8; i++) {
            int c = tid + i * 128;
            int r = c >> 4, in_ = c & 15;
            *(uint4*)&Ks[r * KS_STR + in_ * 8] =
                *(const uint4*)(qbase + (size_t)r * NH * HD + in_ * 8);
        }
    }
    __syncthreads();

    uint32_t qf[8][4];
    {
        int rowQ = wid * 16 + mlo * 8 + l7;
#pragma unroll
        for (int kc = 0; kc < 8; kc++)
            ldsm_x4(qf[kc], ksb + 2 * (rowQ * KS_STR + kc * 16 + mhi * 8));
    }
    __syncthreads();

    float m0 = -1e30f, m1 = -1e30f, l0 = 0.f, l1 = 0.f;
    float o[16][4];
#pragma unroll
    for (int nt = 0; nt < 16; nt++)
#pragma unroll
        for (int r = 0; r < 4; r++) o[nt][r] = 0.f;

    int row0 = qb * 64 + wid * 16 + g;
    int row1 = row0 + 8;

    // B-frag lane geometry (same for Ks scores and Vs PV)
    int bRow = mhi * 8 + l7;   // + np*16
    int bK   = mlo * 8;        // + kc*16

    for (int kt = 0; kt <= qb; kt++) {
        // ---- load K tile [64][128] and VT tile [128][64] ----
        {
            const __half* kb = Kh + (((size_t)b * SS + kt * 64) * NKV + hk) * HD;
#pragma unroll
            for (int i = 0; i < 8; i++) {
                int c = tid + i * 128;
                int r = c >> 4, in_ = c & 15;
                *(uint4*)&Ks[r * KS_STR + in_ * 8] =
                    *(const uint4*)(kb + (size_t)r * NKV * HD + in_ * 8);
            }
            const __half* vb = VT + (((size_t)b * NKV + hk) * HD) * SS + kt * 64;
#pragma unroll
            for (int i = 0; i < 8; i++) {
                int c = tid + i * 128;
                int r = c >> 3, in_ = c & 7;
                *(uint4*)&Vs[r * VS_STR + in_ * 8] =
                    *(const uint4*)(vb + (size_t)r * SS + in_ * 8);
            }
        }
        __syncthreads();

        // ---- scores S[16][64] per warp (ldmatrix B-frags) ----
        float s[8][4];
#pragma unroll
        for (int nt = 0; nt < 8; nt++)
#pragma unroll
            for (int r = 0; r < 4; r++) s[nt][r] = 0.f;

#pragma unroll
        for (int kc = 0; kc < 8; kc++) {
#pragma unroll
            for (int np = 0; np < 4; np++) {
                uint32_t bf[4];
                ldsm_x4(bf, ksb + 2 * ((np * 16 + bRow) * KS_STR + kc * 16 + bK));
                mma_f16(s[2 * np],     qf[kc], &bf[0]);
                mma_f16(s[2 * np + 1], qf[kc], &bf[2]);
            }
        }

        // ---- causal mask on diagonal tile ----
        if (kt == qb) {
#pragma unroll
            for (int nt = 0; nt < 8; nt++) {
                int colb = kt * 64 + nt * 8 + 2 * tg;
#pragma unroll
                for (int e = 0; e < 2; e++) {
                    if (colb + e > row0) s[nt][e]     = -1e30f;
                    if (colb + e > row1) s[nt][2 + e] = -1e30f;
                }
            }
        }

        // ---- online softmax (fp32) ----
        float mx0 = -1e30f, mx1 = -1e30f;
#pragma unroll
        for (int nt = 0; nt < 8; nt++) {
            mx0 = fmaxf(mx0, fmaxf(s[nt][0], s[nt][1]));
            mx1 = fmaxf(mx1, fmaxf(s[nt][2], s[nt][3]));
        }
        mx0 = fmaxf(mx0, __shfl_xor_sync(0xffffffffu, mx0, 1));
        mx0 = fmaxf(mx0, __shfl_xor_sync(0xffffffffu, mx0, 2));
        mx1 = fmaxf(mx1, __shfl_xor_sync(0xffffffffu, mx1, 1));
        mx1 = fmaxf(mx1, __shfl_xor_sync(0xffffffffu, mx1, 2));

        float mn0 = fmaxf(m0, mx0), mn1 = fmaxf(m1, mx1);
        float cr0 = __expf(m0 - mn0), cr1 = __expf(m1 - mn1);
        float lp0 = 0.f, lp1 = 0.f;
#pragma unroll
        for (int nt = 0; nt < 8; nt++) {
            s[nt][0] = __expf(s[nt][0] - mn0);
            s[nt][1] = __expf(s[nt][1] - mn0);
            s[nt][2] = __expf(s[nt][2] - mn1);
            s[nt][3] = __expf(s[nt][3] - mn1);
            lp0 += s[nt][0] + s[nt][1];
            lp1 += s[nt][2] + s[nt][3];
        }
        lp0 += __shfl_xor_sync(0xffffffffu, lp0, 1);
        lp0 += __shfl_xor_sync(0xffffffffu, lp0, 2);
        lp1 += __shfl_xor_sync(0xffffffffu, lp1, 1);
        lp1 += __shfl_xor_sync(0xffffffffu, lp1, 2);
        l0 = l0 * cr0 + lp0;
        l1 = l1 * cr1 + lp1;
        m0 = mn0; m1 = mn1;

#pragma unroll
        for (int nt = 0; nt < 16; nt++) {
            o[nt][0] *= cr0; o[nt][1] *= cr0;
            o[nt][2] *= cr1; o[nt][3] *= cr1;
        }

        // ---- pack P as A-frags (accum layout == A-frag layout) ----
        uint32_t pf[4][4];
#pragma unroll
        for (int kc = 0; kc < 4; kc++) {
            int t0 = 2 * kc, t1 = 2 * kc + 1;
            __half2 h00 = __floats2half2_rn(s[t0][0], s[t0][1]);
            __half2 h01 = __floats2half2_rn(s[t0][2], s[t0][3]);
            __half2 h10 = __floats2half2_rn(s[t1][0], s[t1][1]);
            __half2 h11 = __floats2half2_rn(s[t1][2], s[t1][3]);
            pf[kc][0] = *(uint32_t*)&h00;
            pf[kc][1] = *(uint32_t*)&h01;
            pf[kc][2] = *(uint32_t*)&h10;
            pf[kc][3] = *(uint32_t*)&h11;
        }

        // ---- O += P @ V (ldmatrix VT frags) ----
#pragma unroll
        for (int kc = 0; kc < 4; kc++) {
#pragma unroll
            for (int np = 0; np < 8; np++) {
                uint32_t bf[4];
                ldsm_x4(bf, vsb + 2 * ((np * 16 + bRow) * VS_STR + kc * 16 + bK));
                mma_f16(o[2 * np],     pf[kc], &bf[0]);
                mma_f16(o[2 * np + 1], pf[kc], &bf[2]);
            }
        }
        __syncthreads();
    }

    // ---- epilogue: O /= l, write fp16 ----
    float inv0 = 1.f / l0, inv1 = 1.f / l1;
    __half* ob = O + (((size_t)b * SS) * NH + h) * HD;
#pragma unroll
    for (int nt = 0; nt < 16; nt++) {
        int col = nt * 8 + 2 * tg;
        __half2 v0 = __floats2half2_rn(o[nt][0] * inv0, o[nt][1] * inv0);
        __half2 v1 = __floats2half2_rn(o[nt][2] * inv1, o[nt][3] * inv1);
        *(__half2*)(ob + (size_t)row0 * NH * HD + col) = v0;
        *(__half2*)(ob + (size_t)row1 * NH * HD + col) = v1;
    }
}

// ---------------------------------------------------------------------------
// Launch. ncu capture = 6th launch -> QKV gemm_f16p.
// ---------------------------------------------------------------------------
extern "C" void kernel_launch(void* const* d_in, const int* in_sizes, int n_in,
                              void* d_out, int out_size) {
    const float* hidden = (const float*)d_in[0];
    const float* cosv   = (const float*)d_in[1];
    const float* sinv   = (const float*)d_in[2];
    const float* wq     = (const float*)d_in[3];
    const float* wk     = (const float*)d_in[4];
    const float* wv     = (const float*)d_in[5];
    const float* wo     = (const float*)d_in[6];
    float* out = (float*)d_out;

    void *phs, *pq, *pk, *pv, *pqh, *pkh, *pvT, *pattn, *pwT, *pwo;
    cudaGetSymbolAddress(&phs, g_hs);
    cudaGetSymbolAddress(&pq, g_q);
    cudaGetSymbolAddress(&pk, g_k);
    cudaGetSymbolAddress(&pv, g_v);
    cudaGetSymbolAddress(&pqh, g_qh);
    cudaGetSymbolAddress(&pkh, g_kh);
    cudaGetSymbolAddress(&pvT, g_vT);
    cudaGetSymbolAddress(&pattn, g_attn);
    cudaGetSymbolAddress(&pwT, g_wT);
    cudaGetSymbolAddress(&pwo, g_woT);
    __half* dhs = (__half*)phs;
    float* dq = (float*)pq;
    float* dk = (float*)pk;
    float* dv = (float*)pv;
    __half* dqh = (__half*)pqh;
    __half* dkh = (__half*)pkh;
    __half* dvT = (__half*)pvT;
    __half* dattn = (__half*)pattn;
    __half* dwT = (__half*)pwT;
    __half* dwoT = (__half*)pwo;

    cudaFuncSetAttribute(gemm_f16p, cudaFuncAttributeMaxDynamicSharedMemorySize,
                         GEMM_SMEM);
    cudaFuncSetAttribute(flash_h, cudaFuncAttributeMaxDynamicSharedMemorySize,
                         FLASH_SMEM);

    const int M  = BB * SS;       // 4096
    const int NQ = NH * HD;       // 4096
    const int NK = NKV * HD;      // 1024

    // launches 1-5: preprocessing
    int n8 = BB * SS * HH / 8;
    f2h_copy<<<(n8 + 255) / 256, 256>>>(hidden, dhs, n8);
    transpose_h<<<dim3(NQ / 32, HH / 32), dim3(32, 8)>>>(wq, dwT, HH, NQ);
    transpose_h<<<dim3(NK / 32, HH / 32), dim3(32, 8)>>>(wk, dwT + (size_t)NQ * HH, HH, NK);
    transpose_h<<<dim3(NK / 32, HH / 32), dim3(32, 8)>>>(wv, dwT + (size_t)(NQ + NK) * HH, HH, NK);
    transpose_h<<<dim3(HH / 32, NQ / 32), dim3(32, 8)>>>(wo, dwoT, NQ, HH);

    // launch 6: fused QKV projection (ncu-profiled)
    gemm_f16p<<<dim3(NQKV / TBN, M / TBM), 256, GEMM_SMEM>>>(
        dhs, dwT, dq, dk, dv, M, NQKV, HH, NQ, NQ + NK, NQ, NK, NK);

    // RoPE -> fp16 (q pre-scaled by 1/sqrt(HD))
    const float scl = 1.f / sqrtf((float)HD);
    int tq = BB * SS * NH * 32;
    rope_h<<<(tq + 255) / 256, 256>>>(dq, dqh, cosv, sinv, NH, scl, tq);
    int tk = BB * SS * NKV * 32;
    rope_h<<<(tk + 255) / 256, 256>>>(dk, dkh, cosv, sinv, NKV, 1.f, tk);

    // V transpose to [b,hk,d,s] fp16
    v_transpose<<<dim3(SS / 32, HD / 32, BB * NKV), dim3(32, 8)>>>(dv, dvT);

    // Flash attention (fp16 HMMA)
    flash_h<<<dim3(SS / 64, BB * NH), 128, FLASH_SMEM>>>(dqh, dkh, dvT, dattn);

    // Output projection
    gemm_f16p<<<dim3(HH / TBN, M / TBM), 256, GEMM_SMEM>>>(
        dattn, dwoT, out, out, out, M, HH, NQ, HH, HH, HH, HH, HH);
}

// round 13
// speedup vs baseline: 10.6701x; 1.0188x over previous
#include <cuda_runtime.h>
#include <cuda_fp16.h>
#include <math.h>
#include <stdint.h>

#define BB 2
#define SS 2048
#define HH 4096
#define NH 32
#define NKV 8
#define HD 128

#define NQKV (NH * HD + 2 * NKV * HD)   // 6144 fused output cols

// Scratch (allocation-free rule: __device__ globals)
__device__ __half g_hs[(size_t)BB*SS*HH];         // fp16 hidden
__device__ float  g_q[(size_t)BB*SS*NH*HD];       // f32 q (pre-RoPE)
__device__ float  g_k[(size_t)BB*SS*NKV*HD];
__device__ float  g_v[(size_t)BB*SS*NKV*HD];
__device__ __half g_qh[(size_t)BB*SS*NH*HD];      // fp16 q post-RoPE (pre-scaled)
__device__ __half g_kh[(size_t)BB*SS*NKV*HD];     // fp16 k post-RoPE
__device__ __half g_vT[(size_t)BB*NKV*HD*SS];     // fp16 V transposed [b,hk,d,s]
__device__ __half g_attn[(size_t)BB*SS*NH*HD];    // fp16 attn (O-proj input)
__device__ __half g_wT[(size_t)NQKV*HH];          // fused [6144][4096] K-major fp16
__device__ __half g_woT[(size_t)HH*NH*HD];        // [4096][4096] K-major fp16

// ---------------------------------------------------------------------------
// helpers
// ---------------------------------------------------------------------------
__device__ __forceinline__ uint32_t smem_u32(const void* p) {
    uint32_t a;
    asm("{ .reg .u64 t; cvta.to.shared.u64 t, %1; cvt.u32.u64 %0, t; }"
        : "=r"(a) : "l"(p));
    return a;
}

__device__ __forceinline__ void mma_f16(float* d, const uint32_t* a, const uint32_t* b) {
    asm volatile(
        "mma.sync.aligned.m16n8k16.row.col.f32.f16.f16.f32 "
        "{%0,%1,%2,%3}, {%4,%5,%6,%7}, {%8,%9}, {%0,%1,%2,%3};"
        : "+f"(d[0]), "+f"(d[1]), "+f"(d[2]), "+f"(d[3])
        : "r"(a[0]), "r"(a[1]), "r"(a[2]), "r"(a[3]),
          "r"(b[0]), "r"(b[1]));
}

__device__ __forceinline__ void ldsm_x4(uint32_t* r, uint32_t addr) {
    asm volatile("ldmatrix.sync.aligned.m8n8.x4.shared.b16 {%0,%1,%2,%3}, [%4];"
        : "=r"(r[0]), "=r"(r[1]), "=r"(r[2]), "=r"(r[3]) : "r"(addr));
}

#define CP_ASYNC16(dst, src) \
    asm volatile("cp.async.cg.shared.global [%0], [%1], 16;" \
        :: "r"(dst), "l"(src) : "memory")
#define CP_COMMIT() asm volatile("cp.async.commit_group;" ::: "memory")
#define CP_WAIT1()  asm volatile("cp.async.wait_group 1;" ::: "memory")
#define CP_WAIT0()  asm volatile("cp.async.wait_group 0;" ::: "memory")

// ---------------------------------------------------------------------------
// FP16 HMMA GEMM, cp.async 3-stage pipeline, ldmatrix fragment loads.
// ---------------------------------------------------------------------------
#define TBM 128
#define TBN 128
#define TBK 64
#define NSTG 3
#define OPND_B (TBM * TBK * 2)
#define STAGE_B (2 * OPND_B)
#define GEMM_SMEM (NSTG * STAGE_B)

__global__ __launch_bounds__(256, 2) void gemm_f16p(
        const __half* __restrict__ A, const __half* __restrict__ BT,
        float* __restrict__ C0, float* __restrict__ C1, float* __restrict__ C2,
        int M, int N, int K, int n1, int n2, int ns0, int ns1, int ns2) {
    extern __shared__ char smem[];
    uint32_t sb = smem_u32(smem);

    int tid  = threadIdx.x;
    int lane = tid & 31;
    int w    = tid >> 5;
    int wm   = w & 1;
    int wn   = w >> 1;
    int g    = lane >> 2;
    int tg   = lane & 3;

    int bm = blockIdx.y * TBM, bn = blockIdx.x * TBN;

    int l7  = lane & 7;
    int mlo = (lane >> 3) & 1;
    int mhi = lane >> 4;
    int aRowBase = wm * 64 + mlo * 8 + l7;
    int aSegOff  = mhi;
    int bRowBase = wn * 32 + mhi * 8 + l7;
    int bSegOff  = mlo;

    float acc[4][4][4];
#pragma unroll
    for (int i = 0; i < 4; i++)
#pragma unroll
        for (int j = 0; j < 4; j++)
#pragma unroll
            for (int r = 0; r < 4; r++) acc[i][j][r] = 0.f;

    const int NC = K / TBK;

    auto load_chunk = [&](int i, int s) {
        int k0 = i * TBK;
        uint32_t stA = sb + s * STAGE_B;
        uint32_t stB = stA + OPND_B;
#pragma unroll
        for (int j = 0; j < 4; j++) {
            int lin = tid + j * 256;
            int r = lin >> 3, sg = lin & 7;
            uint32_t dA = stA + r * 128 + ((sg ^ (r & 7)) << 4);
            CP_ASYNC16(dA, &A[(size_t)(bm + r) * K + k0 + sg * 8]);
            uint32_t dB = stB + r * 128 + ((sg ^ (r & 7)) << 4);
            CP_ASYNC16(dB, &BT[(size_t)(bn + r) * K + k0 + sg * 8]);
        }
    };

    load_chunk(0, 0); CP_COMMIT();
    load_chunk(1, 1); CP_COMMIT();

    for (int i = 0; i < NC; i++) {
        CP_WAIT1();
        __syncthreads();
        if (i + 2 < NC) load_chunk(i + 2, (i + 2) % NSTG);
        CP_COMMIT();

        uint32_t cA = sb + (i % NSTG) * STAGE_B;
        uint32_t cB = cA + OPND_B;
#pragma unroll
        for (int kk = 0; kk < 4; kk++) {
            uint32_t afr[4][4], bfr[2][4];
#pragma unroll
            for (int mi = 0; mi < 4; mi++) {
                int row = aRowBase + mi * 16;
                int seg = kk * 2 + aSegOff;
                ldsm_x4(afr[mi], cA + row * 128 + (((seg ^ (row & 7)) & 7) << 4));
            }
#pragma unroll
            for (int np = 0; np < 2; np++) {
                int row = bRowBase + np * 16;
                int seg = kk * 2 + bSegOff;
                ldsm_x4(bfr[np], cB + row * 128 + (((seg ^ (row & 7)) & 7) << 4));
            }
#pragma unroll
            for (int mi = 0; mi < 4; mi++)
#pragma unroll
                for (int np = 0; np < 2; np++) {
                    mma_f16(acc[mi][2 * np],     afr[mi], &bfr[np][0]);
                    mma_f16(acc[mi][2 * np + 1], afr[mi], &bfr[np][2]);
                }
        }
        __syncthreads();
    }

    float* Cp; int ns, coff;
    if (bn < n1)      { Cp = C0; ns = ns0; coff = bn; }
    else if (bn < n2) { Cp = C1; ns = ns1; coff = bn - n1; }
    else              { Cp = C2; ns = ns2; coff = bn - n2; }

#pragma unroll
    for (int mi = 0; mi < 4; mi++) {
#pragma unroll
        for (int ni = 0; ni < 4; ni++) {
            int row = bm + wm * 64 + mi * 16 + g;
            int col = coff + wn * 32 + ni * 8 + 2 * tg;
            float2 lo = {acc[mi][ni][0], acc[mi][ni][1]};
            float2 hi = {acc[mi][ni][2], acc[mi][ni][3]};
            *(float2*)&Cp[(size_t)row * ns + col]       = lo;
            *(float2*)&Cp[(size_t)(row + 8) * ns + col] = hi;
        }
    }
}

// ---------------------------------------------------------------------------
// Preprocessing kernels
// ---------------------------------------------------------------------------
__global__ void transpose_h(const float* __restrict__ in, __half* __restrict__ out,
                            int R, int C) {
    __shared__ float t[32][33];
    int bx = blockIdx.x * 32, by = blockIdx.y * 32;
    int x = bx + threadIdx.x;
#pragma unroll
    for (int j = threadIdx.y; j < 32; j += 8)
        t[j][threadIdx.x] = in[(size_t)(by + j) * C + x];
    __syncthreads();
    int ox = by + threadIdx.x;
#pragma unroll
    for (int j = threadIdx.y; j < 32; j += 8)
        out[(size_t)(bx + j) * R + ox] = __float2half_rn(t[threadIdx.x][j]);
}

__global__ void f2h_copy(const float* __restrict__ in, __half* __restrict__ out, int n8) {
    int i = blockIdx.x * 256 + threadIdx.x;
    if (i >= n8) return;
    float4 v0 = ((const float4*)in)[2 * i];
    float4 v1 = ((const float4*)in)[2 * i + 1];
    __half2* o = (__half2*)out + 4 * (size_t)i;
    o[0] = __floats2half2_rn(v0.x, v0.y);
    o[1] = __floats2half2_rn(v0.z, v0.w);
    o[2] = __floats2half2_rn(v1.x, v1.y);
    o[3] = __floats2half2_rn(v1.z, v1.w);
}

// V transpose: in g_v [b][s][hk][d] f32 -> out g_vT [b][hk][d][s] fp16
__global__ void v_transpose(const float* __restrict__ in, __half* __restrict__ out) {
    __shared__ float t[32][33];
    int s0 = blockIdx.x * 32, d0 = blockIdx.y * 32;
    int bhk = blockIdx.z;
    int b = bhk / NKV, hk = bhk % NKV;
#pragma unroll
    for (int j = threadIdx.y; j < 32; j += 8)
        t[j][threadIdx.x] =
            in[(((size_t)b * SS + s0 + j) * NKV + hk) * HD + d0 + threadIdx.x];
    __syncthreads();
#pragma unroll
    for (int j = threadIdx.y; j < 32; j += 8)
        out[(((size_t)b * NKV + hk) * HD + d0 + j) * SS + s0 + threadIdx.x] =
            __float2half_rn(t[threadIdx.x][j]);
}

__global__ void rope_h(const float* __restrict__ x, __half* __restrict__ out,
                       const float* __restrict__ cos_t, const float* __restrict__ sin_t,
                       int nheads, float scl, int total) {
    int idx = blockIdx.x * blockDim.x + threadIdx.x;
    if (idx >= total) return;
    int d2 = idx % 32;
    int h  = (idx / 32) % nheads;
    int bs = idx / (32 * nheads);
    int d  = 2 * d2;

    const float* cb = cos_t + (size_t)bs * HD;
    const float* sb = sin_t + (size_t)bs * HD;
    const float* px = x + ((size_t)bs * nheads + h) * HD;
    __half* po = out + ((size_t)bs * nheads + h) * HD;

    float xa0 = px[d],      xa1 = px[d + 1];
    float xb0 = px[d + 64], xb1 = px[d + 65];
    float lo0 = (xa0 * cb[d]      - xb0 * sb[d])      * scl;
    float lo1 = (xa1 * cb[d + 1]  - xb1 * sb[d + 1])  * scl;
    float hi0 = (xb0 * cb[d + 64] + xa0 * sb[d + 64]) * scl;
    float hi1 = (xb1 * cb[d + 65] + xa1 * sb[d + 65]) * scl;
    *(__half2*)(po + d)      = __floats2half2_rn(lo0, lo1);
    *(__half2*)(po + d + 64) = __floats2half2_rn(hi0, hi1);
}

// ---------------------------------------------------------------------------
// Flash attention, fp16 HMMA, ldmatrix frags, cp.async double-buffered K/V.
// ---------------------------------------------------------------------------
#define KS_STR 136
#define VS_STR 72
#define TILE_HLV (64 * KS_STR + HD * VS_STR)    // halves per buffer (17920)
#define FLASH_SMEM (2 * TILE_HLV * 2)           // 71680 B

__global__ __launch_bounds__(128) void flash_h(const __half* __restrict__ Qh,
                                               const __half* __restrict__ Kh,
                                               const __half* __restrict__ VT,
                                               __half* __restrict__ O) {
    extern __shared__ __half sm[];

    int tid  = threadIdx.x;
    int lane = tid & 31;
    int wid  = tid >> 5;           // 0..3
    int g    = lane >> 2;
    int tg   = lane & 3;
    int l7   = lane & 7;
    int mlo  = (lane >> 3) & 1;
    int mhi  = lane >> 4;

    int qb = blockIdx.x;
    int bh = blockIdx.y;
    int b = bh / NH, h = bh % NH;
    int hk = h / (NH / NKV);

    uint32_t smb = smem_u32(sm);
    const __half* kb0 = Kh + ((size_t)b * SS * NKV + hk) * HD;
    const __half* vb0 = VT + (((size_t)b * NKV + hk) * HD) * SS;

    // ---- stage Q tile into buffer-0 K area, build persistent Q fragments ----
    {
        const __half* qbase = Qh + (((size_t)b * SS + qb * 64) * NH + h) * HD;
#pragma unroll
        for (int i = 0; i < 8; i++) {
            int c = tid + i * 128;
            int r = c >> 4, in_ = c & 15;
            *(uint4*)&sm[r * KS_STR + in_ * 8] =
                *(const uint4*)(qbase + (size_t)r * NH * HD + in_ * 8);
        }
    }
    __syncthreads();

    uint32_t qf[8][4];
    {
        int rowQ = wid * 16 + mlo * 8 + l7;
#pragma unroll
        for (int kc = 0; kc < 8; kc++)
            ldsm_x4(qf[kc], smb + 2 * (rowQ * KS_STR + kc * 16 + mhi * 8));
    }
    __syncthreads();   // all frags read before cp.async overwrites buffer 0

    // ---- async K/V tile loader into buffer s ----
    auto issue_tile = [&](int kt, int s) {
        uint32_t ksb = smb + 2 * (s * TILE_HLV);
        uint32_t vsb = ksb + 2 * (64 * KS_STR);
        const __half* kb = kb0 + (size_t)(kt * 64) * NKV * HD;
        const __half* vb = vb0 + kt * 64;
#pragma unroll
        for (int i = 0; i < 8; i++) {
            int c = tid + i * 128;
            int r = c >> 4, in_ = c & 15;
            CP_ASYNC16(ksb + 2 * (r * KS_STR + in_ * 8),
                       kb + (size_t)r * NKV * HD + in_ * 8);
        }
#pragma unroll
        for (int i = 0; i < 8; i++) {
            int c = tid + i * 128;
            int r = c >> 3, in_ = c & 7;
            CP_ASYNC16(vsb + 2 * (r * VS_STR + in_ * 8),
                       vb + (size_t)r * SS + in_ * 8);
        }
    };

    float m0 = -1e30f, m1 = -1e30f, l0 = 0.f, l1 = 0.f;
    float o[16][4];
#pragma unroll
    for (int nt = 0; nt < 16; nt++)
#pragma unroll
        for (int r = 0; r < 4; r++) o[nt][r] = 0.f;

    int row0 = qb * 64 + wid * 16 + g;
    int row1 = row0 + 8;

    int bRow = mhi * 8 + l7;   // + np*16
    int bK   = mlo * 8;        // + kc*16

    issue_tile(0, 0); CP_COMMIT();

    for (int kt = 0; kt <= qb; kt++) {
        if (kt < qb) {
            issue_tile(kt + 1, (kt + 1) & 1);
            CP_COMMIT();
            CP_WAIT1();
        } else {
            CP_WAIT0();
        }
        __syncthreads();

        uint32_t ksb = smb + 2 * ((kt & 1) * TILE_HLV);
        uint32_t vsb = ksb + 2 * (64 * KS_STR);

        // ---- scores S[16][64] per warp (ldmatrix B-frags) ----
        float s[8][4];
#pragma unroll
        for (int nt = 0; nt < 8; nt++)
#pragma unroll
            for (int r = 0; r < 4; r++) s[nt][r] = 0.f;

#pragma unroll
        for (int kc = 0; kc < 8; kc++) {
#pragma unroll
            for (int np = 0; np < 4; np++) {
                uint32_t bf[4];
                ldsm_x4(bf, ksb + 2 * ((np * 16 + bRow) * KS_STR + kc * 16 + bK));
                mma_f16(s[2 * np],     qf[kc], &bf[0]);
                mma_f16(s[2 * np + 1], qf[kc], &bf[2]);
            }
        }

        // ---- causal mask on diagonal tile ----
        if (kt == qb) {
#pragma unroll
            for (int nt = 0; nt < 8; nt++) {
                int colb = kt * 64 + nt * 8 + 2 * tg;
#pragma unroll
                for (int e = 0; e < 2; e++) {
                    if (colb + e > row0) s[nt][e]     = -1e30f;
                    if (colb + e > row1) s[nt][2 + e] = -1e30f;
                }
            }
        }

        // ---- online softmax (fp32) ----
        float mx0 = -1e30f, mx1 = -1e30f;
#pragma unroll
        for (int nt = 0; nt < 8; nt++) {
            mx0 = fmaxf(mx0, fmaxf(s[nt][0], s[nt][1]));
            mx1 = fmaxf(mx1, fmaxf(s[nt][2], s[nt][3]));
        }
        mx0 = fmaxf(mx0, __shfl_xor_sync(0xffffffffu, mx0, 1));
        mx0 = fmaxf(mx0, __shfl_xor_sync(0xffffffffu, mx0, 2));
        mx1 = fmaxf(mx1, __shfl_xor_sync(0xffffffffu, mx1, 1));
        mx1 = fmaxf(mx1, __shfl_xor_sync(0xffffffffu, mx1, 2));

        float mn0 = fmaxf(m0, mx0), mn1 = fmaxf(m1, mx1);
        float cr0 = __expf(m0 - mn0), cr1 = __expf(m1 - mn1);
        float lp0 = 0.f, lp1 = 0.f;
#pragma unroll
        for (int nt = 0; nt < 8; nt++) {
            s[nt][0] = __expf(s[nt][0] - mn0);
            s[nt][1] = __expf(s[nt][1] - mn0);
            s[nt][2] = __expf(s[nt][2] - mn1);
            s[nt][3] = __expf(s[nt][3] - mn1);
            lp0 += s[nt][0] + s[nt][1];
            lp1 += s[nt][2] + s[nt][3];
        }
        lp0 += __shfl_xor_sync(0xffffffffu, lp0, 1);
        lp0 += __shfl_xor_sync(0xffffffffu, lp0, 2);
        lp1 += __shfl_xor_sync(0xffffffffu, lp1, 1);
        lp1 += __shfl_xor_sync(0xffffffffu, lp1, 2);
        l0 = l0 * cr0 + lp0;
        l1 = l1 * cr1 + lp1;
        m0 = mn0; m1 = mn1;

#pragma unroll
        for (int nt = 0; nt < 16; nt++) {
            o[nt][0] *= cr0; o[nt][1] *= cr0;
            o[nt][2] *= cr1; o[nt][3] *= cr1;
        }

        // ---- pack P as A-frags ----
        uint32_t pf[4][4];
#pragma unroll
        for (int kc = 0; kc < 4; kc++) {
            int t0 = 2 * kc, t1 = 2 * kc + 1;
            __half2 h00 = __floats2half2_rn(s[t0][0], s[t0][1]);
            __half2 h01 = __floats2half2_rn(s[t0][2], s[t0][3]);
            __half2 h10 = __floats2half2_rn(s[t1][0], s[t1][1]);
            __half2 h11 = __floats2half2_rn(s[t1][2], s[t1][3]);
            pf[kc][0] = *(uint32_t*)&h00;
            pf[kc][1] = *(uint32_t*)&h01;
            pf[kc][2] = *(uint32_t*)&h10;
            pf[kc][3] = *(uint32_t*)&h11;
        }

        // ---- O += P @ V (ldmatrix VT frags) ----
#pragma unroll
        for (int kc = 0; kc < 4; kc++) {
#pragma unroll
            for (int np = 0; np < 8; np++) {
                uint32_t bf[4];
                ldsm_x4(bf, vsb + 2 * ((np * 16 + bRow) * VS_STR + kc * 16 + bK));
                mma_f16(o[2 * np],     pf[kc], &bf[0]);
                mma_f16(o[2 * np + 1], pf[kc], &bf[2]);
            }
        }
        __syncthreads();
    }

    // ---- epilogue: O /= l, write fp16 ----
    float inv0 = 1.f / l0, inv1 = 1.f / l1;
    __half* ob = O + (((size_t)b * SS) * NH + h) * HD;
#pragma unroll
    for (int nt = 0; nt < 16; nt++) {
        int col = nt * 8 + 2 * tg;
        __half2 v0 = __floats2half2_rn(o[nt][0] * inv0, o[nt][1] * inv0);
        __half2 v1 = __floats2half2_rn(o[nt][2] * inv1, o[nt][3] * inv1);
        *(__half2*)(ob + (size_t)row0 * NH * HD + col) = v0;
        *(__half2*)(ob + (size_t)row1 * NH * HD + col) = v1;
    }
}

// ---------------------------------------------------------------------------
// Launch
// ---------------------------------------------------------------------------
extern "C" void kernel_launch(void* const* d_in, const int* in_sizes, int n_in,
                              void* d_out, int out_size) {
    const float* hidden = (const float*)d_in[0];
    const float* cosv   = (const float*)d_in[1];
    const float* sinv   = (const float*)d_in[2];
    const float* wq     = (const float*)d_in[3];
    const float* wk     = (const float*)d_in[4];
    const float* wv     = (const float*)d_in[5];
    const float* wo     = (const float*)d_in[6];
    float* out = (float*)d_out;

    void *phs, *pq, *pk, *pv, *pqh, *pkh, *pvT, *pattn, *pwT, *pwo;
    cudaGetSymbolAddress(&phs, g_hs);
    cudaGetSymbolAddress(&pq, g_q);
    cudaGetSymbolAddress(&pk, g_k);
    cudaGetSymbolAddress(&pv, g_v);
    cudaGetSymbolAddress(&pqh, g_qh);
    cudaGetSymbolAddress(&pkh, g_kh);
    cudaGetSymbolAddress(&pvT, g_vT);
    cudaGetSymbolAddress(&pattn, g_attn);
    cudaGetSymbolAddress(&pwT, g_wT);
    cudaGetSymbolAddress(&pwo, g_woT);
    __half* dhs = (__half*)phs;
    float* dq = (float*)pq;
    float* dk = (float*)pk;
    float* dv = (float*)pv;
    __half* dqh = (__half*)pqh;
    __half* dkh = (__half*)pkh;
    __half* dvT = (__half*)pvT;
    __half* dattn = (__half*)pattn;
    __half* dwT = (__half*)pwT;
    __half* dwoT = (__half*)pwo;

    cudaFuncSetAttribute(gemm_f16p, cudaFuncAttributeMaxDynamicSharedMemorySize,
                         GEMM_SMEM);
    cudaFuncSetAttribute(flash_h, cudaFuncAttributeMaxDynamicSharedMemorySize,
                         FLASH_SMEM);

    const int M  = BB * SS;       // 4096
    const int NQ = NH * HD;       // 4096
    const int NK = NKV * HD;      // 1024

    // preprocessing
    int n8 = BB * SS * HH / 8;
    f2h_copy<<<(n8 + 255) / 256, 256>>>(hidden, dhs, n8);
    transpose_h<<<dim3(NQ / 32, HH / 32), dim3(32, 8)>>>(wq, dwT, HH, NQ);
    transpose_h<<<dim3(NK / 32, HH / 32), dim3(32, 8)>>>(wk, dwT + (size_t)NQ * HH, HH, NK);
    transpose_h<<<dim3(NK / 32, HH / 32), dim3(32, 8)>>>(wv, dwT + (size_t)(NQ + NK) * HH, HH, NK);
    transpose_h<<<dim3(HH / 32, NQ / 32), dim3(32, 8)>>>(wo, dwoT, NQ, HH);

    // fused QKV projection
    gemm_f16p<<<dim3(NQKV / TBN, M / TBM), 256, GEMM_SMEM>>>(
        dhs, dwT, dq, dk, dv, M, NQKV, HH, NQ, NQ + NK, NQ, NK, NK);

    // RoPE -> fp16 (q pre-scaled by 1/sqrt(HD))
    const float scl = 1.f / sqrtf((float)HD);
    int tq = BB * SS * NH * 32;
    rope_h<<<(tq + 255) / 256, 256>>>(dq, dqh, cosv, sinv, NH, scl, tq);
    int tk = BB * SS * NKV * 32;
    rope_h<<<(tk + 255) / 256, 256>>>(dk, dkh, cosv, sinv, NKV, 1.f, tk);

    // V transpose to [b,hk,d,s] fp16
    v_transpose<<<dim3(SS / 32, HD / 32, BB * NKV), dim3(32, 8)>>>(dv, dvT);

    // Flash attention (fp16 HMMA, double-buffered cp.async)
    flash_h<<<dim3(SS / 64, BB * NH), 128, FLASH_SMEM>>>(dqh, dkh, dvT, dattn);

    // Output projection
    gemm_f16p<<<dim3(HH / TBN, M / TBM), 256, GEMM_SMEM>>>(
        dattn, dwoT, out, out, out, M, HH, NQ, HH, HH, HH, HH, HH);
}